// round 4
// baseline (speedup 1.0000x reference)
#include <cuda_runtime.h>
#include <math.h>
#include <stdint.h>

// ---------------- problem constants (fixed shapes) ----------------
#define BATCH   2
#define NATOM   2048
#define DATOM   128
#define NHEAD   4
#define DHEAD   32
#define DFF     512
#define DMODEL  512
#define NPAIR   16384
#define NTOK    512
#define ROWS    (BATCH*NATOM)      // 4096

// ---------------- static device scratch (no runtime allocs) ----------------
__device__ float g_qn    [ROWS*DATOM];
__device__ float g_qkvg  [ROWS*4*DATOM];      // [Q|K|V|G] per row, stride 512
__device__ float g_attout[ROWS*DATOM];
__device__ float g_oproj [ROWS*DATOM];
__device__ float g_q1    [ROWS*DATOM];
__device__ float g_h     [ROWS*DATOM];
__device__ float g_u     [ROWS*DFF];
__device__ float g_v     [ROWS*DFF];
__device__ float g_feat  [ROWS*DMODEL];
__device__ float g_bias  [(size_t)BATCH*NHEAD*NATOM*NATOM];  // 134MB, only in-group slots touched
__device__ int   g_winner[(size_t)BATCH*NATOM*NATOM];        // 33MB,  only in-group slots touched
__device__ int   g_gs[ROWS], g_ge[ROWS];          // per-atom group [start,end) (batch-local)
__device__ int   g_ts[BATCH*NTOK], g_tc[BATCH*NTOK];  // per-token start/count

// ---------------- helpers ----------------
__device__ __forceinline__ int d_lower_bound(const int* a, int n, int v) {
    int lo = 0, hi = n;
    while (lo < hi) { int m = (lo + hi) >> 1; if (a[m] < v) lo = m + 1; else hi = m; }
    return lo;
}
__device__ __forceinline__ int d_upper_bound(const int* a, int n, int v) {
    int lo = 0, hi = n;
    while (lo < hi) { int m = (lo + hi) >> 1; if (a[m] <= v) lo = m + 1; else hi = m; }
    return lo;
}

// ---------------- LayerNorm: one warp per row of 128 ----------------
__global__ void k_ln(const float* __restrict__ x, const float* __restrict__ g,
                     const float* __restrict__ b, float* __restrict__ y) {
    int warp = (blockIdx.x * blockDim.x + threadIdx.x) >> 5;
    int lane = threadIdx.x & 31;
    if (warp >= ROWS) return;
    const float* xr = x + (size_t)warp * DATOM;
    float v0 = xr[lane], v1 = xr[lane+32], v2 = xr[lane+64], v3 = xr[lane+96];
    float s  = v0+v1+v2+v3;
    float sq = v0*v0+v1*v1+v2*v2+v3*v3;
    #pragma unroll
    for (int o = 16; o; o >>= 1) {
        s  += __shfl_xor_sync(0xffffffffu, s,  o);
        sq += __shfl_xor_sync(0xffffffffu, sq, o);
    }
    float mean = s * (1.0f/DATOM);
    float var  = sq * (1.0f/DATOM) - mean*mean;
    float inv  = rsqrtf(var + 1e-5f);
    float* yr = y + (size_t)warp * DATOM;
    yr[lane]    = (v0-mean)*inv*g[lane]    + b[lane];
    yr[lane+32] = (v1-mean)*inv*g[lane+32] + b[lane+32];
    yr[lane+64] = (v2-mean)*inv*g[lane+64] + b[lane+64];
    yr[lane+96] = (v3-mean)*inv*g[lane+96] + b[lane+96];
}

// ---------------- fp32 GEMM, C[M,N] = A[M,K] @ B[K,N], 64x64 tile, 4x4/thread ----------------
// requires M%64==0, N%64==0, K%16==0
__global__ __launch_bounds__(256) void k_gemm(int M, int N, int K,
    const float* __restrict__ A, int lda,
    const float* __restrict__ B, int ldb,
    float* __restrict__ C, int ldc) {
    __shared__ float As[16][65];
    __shared__ float Bs[16][64];
    int tid = threadIdx.x;
    int tx = tid & 15, ty = tid >> 4;
    int brow = blockIdx.y * 64, bcol = blockIdx.x * 64;
    int arow = tid >> 2, ac4 = (tid & 3) << 2;   // A tile: 64 x 16
    int brw  = ty,       bc4 = tx << 2;          // B tile: 16 x 64
    float acc[4][4] = {};
    for (int k0 = 0; k0 < K; k0 += 16) {
        float4 av = *(const float4*)(A + (size_t)(brow + arow) * lda + k0 + ac4);
        As[ac4+0][arow] = av.x; As[ac4+1][arow] = av.y;
        As[ac4+2][arow] = av.z; As[ac4+3][arow] = av.w;
        *(float4*)&Bs[brw][bc4] =
            *(const float4*)(B + (size_t)(k0 + brw) * ldb + bcol + bc4);
        __syncthreads();
        #pragma unroll
        for (int k = 0; k < 16; k++) {
            float a[4], bb[4];
            #pragma unroll
            for (int i = 0; i < 4; i++) a[i]  = As[k][(ty<<2)+i];
            #pragma unroll
            for (int j = 0; j < 4; j++) bb[j] = Bs[k][(tx<<2)+j];
            #pragma unroll
            for (int i = 0; i < 4; i++)
                #pragma unroll
                for (int j = 0; j < 4; j++)
                    acc[i][j] += a[i]*bb[j];
        }
        __syncthreads();
    }
    #pragma unroll
    for (int i = 0; i < 4; i++) {
        float* cr = C + (size_t)(brow + (ty<<2) + i) * ldc + bcol + (tx<<2);
        #pragma unroll
        for (int j = 0; j < 4; j++) cr[j] = acc[i][j];
    }
}

// ---------------- per-atom token-group ranges (token_idx sorted per batch) ----------------
__global__ void k_groups(const int* __restrict__ tok) {
    int i = blockIdx.x * blockDim.x + threadIdx.x;
    if (i >= ROWS) return;
    int b = i / NATOM, ii = i % NATOM;
    const int* t = tok + b * NATOM;
    int v = t[ii];
    g_gs[i] = d_lower_bound(t, NATOM, v);
    g_ge[i] = d_upper_bound(t, NATOM, v);
}

// ---------------- zero only in-group bias/winner slots ----------------
__global__ void k_zero_inner() {
    int i = blockIdx.x;                 // atom row, 0..ROWS-1
    int b = i / NATOM, ii = i % NATOM;
    int s = g_gs[i], e = g_ge[i], len = e - s;
    for (int idx = threadIdx.x; idx < len * NHEAD; idx += blockDim.x) {
        int j = s + idx / NHEAD, h = idx % NHEAD;
        g_bias[(((size_t)(b*NHEAD + h) * NATOM + ii) * NATOM) + j] = 0.0f;
    }
    for (int idx = threadIdx.x; idx < len; idx += blockDim.x)
        g_winner[((size_t)(b*NATOM + ii) * NATOM) + (s + idx)] = -1;
}

// ---------------- pair scatter: pass 1 (last-write-wins via atomicMax on pair idx) ----------------
__global__ void k_scatmax(const int* __restrict__ plmidx, const int* __restrict__ tok) {
    int gid = blockIdx.x * blockDim.x + threadIdx.x;
    if (gid >= BATCH * NPAIR) return;
    int b = gid / NPAIR, p = gid % NPAIR;
    int src = plmidx[(size_t)gid*2], dst = plmidx[(size_t)gid*2 + 1];
    if (tok[b*NATOM + src] == tok[b*NATOM + dst])
        atomicMax(&g_winner[((size_t)(b*NATOM + src) * NATOM) + dst], p);
}

// ---------------- pair scatter: pass 2 (winning pair writes bias for all heads) ----------------
__global__ void k_scatwrite(const int* __restrict__ plmidx, const int* __restrict__ tok,
                            const float* __restrict__ p_lm,
                            const float* __restrict__ pb_w, const float* __restrict__ pb_b) {
    int gid = blockIdx.x * blockDim.x + threadIdx.x;
    if (gid >= BATCH * NPAIR) return;
    int b = gid / NPAIR, p = gid % NPAIR;
    int src = plmidx[(size_t)gid*2], dst = plmidx[(size_t)gid*2 + 1];
    if (tok[b*NATOM + src] != tok[b*NATOM + dst]) return;
    if (g_winner[((size_t)(b*NATOM + src) * NATOM) + dst] != p) return;
    const float* pl = p_lm + (size_t)gid * 16;
    #pragma unroll
    for (int h = 0; h < NHEAD; h++) {
        float val = pb_b[h];
        #pragma unroll
        for (int k = 0; k < 16; k++) val += pl[k] * pb_w[k*NHEAD + h];
        g_bias[(((size_t)(b*NHEAD + h) * NATOM + src) * NATOM) + dst] = val;
    }
}

// ---------------- block-diagonal attention: 1 block/atom, 1 warp/head, lane=dim ----------------
__global__ void k_attn() {
    int i = blockIdx.x;                   // global atom row
    int b = i / NATOM, ii = i % NATOM;
    int h = threadIdx.x >> 5, lane = threadIdx.x & 31;
    int s = g_gs[i], e = g_ge[i];
    const float* qrow = g_qkvg + (size_t)i * 512;
    float qd = qrow[h*DHEAD + lane];
    const float* biasrow = g_bias + ((size_t)(b*NHEAD + h) * NATOM + ii) * NATOM;
    float m = -1e30f, l = 0.0f, acc = 0.0f;
    for (int j = s; j < e; j++) {
        const float* row = g_qkvg + (size_t)(b*NATOM + j) * 512;
        float sc = qd * row[DATOM + h*DHEAD + lane];   // K at offset 128
        #pragma unroll
        for (int o = 16; o; o >>= 1) sc += __shfl_xor_sync(0xffffffffu, sc, o);
        sc = sc * 0.17677669529663687f + biasrow[j];
        float mn = fmaxf(m, sc);
        float corr = __expf(m - mn);
        float w = __expf(sc - mn);
        l = l * corr + w;
        acc = acc * corr + w * row[2*DATOM + h*DHEAD + lane];  // V at offset 256
        m = mn;
    }
    g_attout[(size_t)i * DATOM + h*DHEAD + lane] = acc / l;
}

// ---------------- epilogues ----------------
__global__ void k_gate(const float* __restrict__ c_atom) {
    int idx = blockIdx.x * blockDim.x + threadIdx.x;
    if (idx >= ROWS * DATOM) return;
    int row = idx / DATOM, c = idx % DATOM;
    float g = g_qkvg[(size_t)row * 512 + 3*DATOM + c];     // G at offset 384
    float sig = 1.0f / (1.0f + __expf(-g));
    g_q1[idx] = c_atom[idx] + sig * g_oproj[idx];
}
__global__ void k_swiglu() {
    int idx = blockIdx.x * blockDim.x + threadIdx.x;
    if (idx >= ROWS * DFF) return;
    float x = g_u[idx];
    g_u[idx] = (x / (1.0f + __expf(-x))) * g_v[idx];
}
__global__ void k_resadd() {
    int idx = blockIdx.x * blockDim.x + threadIdx.x;
    if (idx >= ROWS * DATOM) return;
    g_q1[idx] += g_oproj[idx];
}

// ---------------- token ranges + segment mean ----------------
__global__ void k_tokranges(const int* __restrict__ tok) {
    int t = blockIdx.x * blockDim.x + threadIdx.x;
    if (t >= BATCH * NTOK) return;
    int b = t / NTOK, tt = t % NTOK;
    const int* ta = tok + b * NATOM;
    int lo = d_lower_bound(ta, NATOM, tt);
    int hi = d_upper_bound(ta, NATOM, tt);
    g_ts[t] = lo; g_tc[t] = hi - lo;
}
__global__ void k_segmean(const float* __restrict__ tok_b, float* __restrict__ out) {
    int seg = blockIdx.x;                // 0..BATCH*NTOK-1
    int b = seg / NTOK;
    int d = threadIdx.x;                 // 0..511
    int s = g_ts[seg], c = g_tc[seg];
    float sum = 0.0f;
    for (int k = 0; k < c; k++)
        sum += g_feat[(size_t)(b*NATOM + s + k) * DMODEL + d];
    out[(size_t)seg * DMODEL + d] = c ? (sum / (float)c + tok_b[d]) : 0.0f;
}

// ---------------- launch ----------------
extern "C" void kernel_launch(void* const* d_in, const int* in_sizes, int n_in,
                              void* d_out, int out_size) {
    // n_tokens may or may not be materialized as input 4 (scalar). Detect.
    int shift = (in_sizes[4] == 1) ? 1 : 0;
    const float* c_atom    = (const float*)d_in[0];
    const float* p_lm      = (const float*)d_in[1];
    const int*   p_lm_idx  = (const int*)  d_in[2];
    const int*   token_idx = (const int*)  d_in[3];
    const float* ln_attn_g = (const float*)d_in[4+shift];
    const float* ln_attn_b = (const float*)d_in[5+shift];
    const float* w_q       = (const float*)d_in[6+shift];
    const float* w_k       = (const float*)d_in[7+shift];
    const float* w_v       = (const float*)d_in[8+shift];
    const float* w_g       = (const float*)d_in[9+shift];
    const float* w_o       = (const float*)d_in[10+shift];
    const float* pb_w      = (const float*)d_in[11+shift];
    const float* pb_b      = (const float*)d_in[12+shift];
    const float* ln_ff_g   = (const float*)d_in[13+shift];
    const float* ln_ff_b   = (const float*)d_in[14+shift];
    const float* sw_w1     = (const float*)d_in[15+shift];
    const float* sw_w2     = (const float*)d_in[16+shift];
    const float* sw_w3     = (const float*)d_in[17+shift];
    const float* tok_w     = (const float*)d_in[18+shift];
    const float* tok_b     = (const float*)d_in[19+shift];
    float* out = (float*)d_out;

    float *p_qn, *p_qkvg, *p_attout, *p_oproj, *p_q1, *p_h, *p_u, *p_v, *p_feat;
    cudaGetSymbolAddress((void**)&p_qn,     g_qn);
    cudaGetSymbolAddress((void**)&p_qkvg,   g_qkvg);
    cudaGetSymbolAddress((void**)&p_attout, g_attout);
    cudaGetSymbolAddress((void**)&p_oproj,  g_oproj);
    cudaGetSymbolAddress((void**)&p_q1,     g_q1);
    cudaGetSymbolAddress((void**)&p_h,      g_h);
    cudaGetSymbolAddress((void**)&p_u,      g_u);
    cudaGetSymbolAddress((void**)&p_v,      g_v);
    cudaGetSymbolAddress((void**)&p_feat,   g_feat);

    // 1. q_n = LN(c_atom)
    k_ln<<<ROWS/4, 128>>>(c_atom, ln_attn_g, ln_attn_b, p_qn);

    // 2. QKVG projections into g_qkvg (ldc = 512, column-offset per weight)
    {
        dim3 grid(DATOM/64, ROWS/64);
        k_gemm<<<grid, 256>>>(ROWS, DATOM, DATOM, p_qn, DATOM, w_q, DATOM, p_qkvg + 0*DATOM, 4*DATOM);
        k_gemm<<<grid, 256>>>(ROWS, DATOM, DATOM, p_qn, DATOM, w_k, DATOM, p_qkvg + 1*DATOM, 4*DATOM);
        k_gemm<<<grid, 256>>>(ROWS, DATOM, DATOM, p_qn, DATOM, w_v, DATOM, p_qkvg + 2*DATOM, 4*DATOM);
        k_gemm<<<grid, 256>>>(ROWS, DATOM, DATOM, p_qn, DATOM, w_g, DATOM, p_qkvg + 3*DATOM, 4*DATOM);
    }

    // 3. token groups + sparse bias scatter (last-write-wins)
    k_groups<<<ROWS/256, 256>>>(token_idx);
    k_zero_inner<<<ROWS, 128>>>();
    k_scatmax<<<(BATCH*NPAIR)/256, 256>>>(p_lm_idx, token_idx);
    k_scatwrite<<<(BATCH*NPAIR)/256, 256>>>(p_lm_idx, token_idx, p_lm, pb_w, pb_b);

    // 4. block-diagonal attention
    k_attn<<<ROWS, 128>>>();

    // 5. output projection + gated residual
    {
        dim3 grid(DATOM/64, ROWS/64);
        k_gemm<<<grid, 256>>>(ROWS, DATOM, DATOM, p_attout, DATOM, w_o, DATOM, p_oproj, DATOM);
    }
    k_gate<<<(ROWS*DATOM)/256, 256>>>(c_atom);

    // 6. FFN (SwiGLU) with residual
    k_ln<<<ROWS/4, 128>>>(p_q1, ln_ff_g, ln_ff_b, p_h);
    {
        dim3 gridff(DFF/64, ROWS/64);
        k_gemm<<<gridff, 256>>>(ROWS, DFF, DATOM, p_h, DATOM, sw_w1, DFF, p_u, DFF);
        k_gemm<<<gridff, 256>>>(ROWS, DFF, DATOM, p_h, DATOM, sw_w2, DFF, p_v, DFF);
    }
    k_swiglu<<<(ROWS*DFF)/256, 256>>>();
    {
        dim3 grid(DATOM/64, ROWS/64);
        k_gemm<<<grid, 256>>>(ROWS, DATOM, DFF, p_u, DFF, sw_w3, DATOM, p_oproj, DATOM);
    }
    k_resadd<<<(ROWS*DATOM)/256, 256>>>();

    // 7. token projection (bias folded into segment mean)
    {
        dim3 grid(DMODEL/64, ROWS/64);
        k_gemm<<<grid, 256>>>(ROWS, DMODEL, DATOM, p_q1, DATOM, tok_w, DMODEL, p_feat, DMODEL);
    }

    // 8. segment mean -> output
    k_tokranges<<<(BATCH*NTOK)/256, 256>>>(token_idx);
    k_segmean<<<BATCH*NTOK, DMODEL>>>(tok_b, out);
}

// round 5
// speedup vs baseline: 1.2544x; 1.2544x over previous
#include <cuda_runtime.h>
#include <math.h>
#include <stdint.h>

// ---------------- problem constants (fixed shapes) ----------------
#define BATCH   2
#define NATOM   2048
#define DATOM   128
#define NHEAD   4
#define DHEAD   32
#define DFF     512
#define DMODEL  512
#define NPAIR   16384
#define NTOK    512
#define ROWS    (BATCH*NATOM)      // 4096

// ---------------- static device scratch (no runtime allocs) ----------------
__device__ float g_qn    [ROWS*DATOM];
__device__ float g_qkvg  [ROWS*4*DATOM];      // [Q|K|V|G] per row, stride 512
__device__ float g_attout[ROWS*DATOM];
__device__ float g_q1    [ROWS*DATOM];
__device__ float g_h     [ROWS*DATOM];
__device__ float g_u     [ROWS*DFF];          // silu(h@w1)*(h@w2) fused
__device__ float g_feat  [ROWS*DMODEL];
__device__ float g_bias  [(size_t)BATCH*NHEAD*NATOM*NATOM];  // only in-group slots touched
__device__ int   g_winner[(size_t)BATCH*NATOM*NATOM];        // only in-group slots touched
__device__ int   g_gs[ROWS], g_ge[ROWS];              // per-atom group [start,end)
__device__ int   g_ts[BATCH*NTOK], g_tc[BATCH*NTOK];  // per-token start/count

// ---------------- helpers ----------------
__device__ __forceinline__ int d_lower_bound(const int* a, int n, int v) {
    int lo = 0, hi = n;
    while (lo < hi) { int m = (lo + hi) >> 1; if (a[m] < v) lo = m + 1; else hi = m; }
    return lo;
}
__device__ __forceinline__ int d_upper_bound(const int* a, int n, int v) {
    int lo = 0, hi = n;
    while (lo < hi) { int m = (lo + hi) >> 1; if (a[m] <= v) lo = m + 1; else hi = m; }
    return lo;
}
__device__ __forceinline__ float d_sigmoid(float x) { return 1.0f / (1.0f + __expf(-x)); }

// ---------------- LayerNorm: one warp per row of 128 ----------------
__global__ void k_ln(const float* __restrict__ x, const float* __restrict__ g,
                     const float* __restrict__ b, float* __restrict__ y) {
    int warp = (blockIdx.x * blockDim.x + threadIdx.x) >> 5;
    int lane = threadIdx.x & 31;
    if (warp >= ROWS) return;
    const float* xr = x + (size_t)warp * DATOM;
    float v0 = xr[lane], v1 = xr[lane+32], v2 = xr[lane+64], v3 = xr[lane+96];
    float s  = v0+v1+v2+v3;
    float sq = v0*v0+v1*v1+v2*v2+v3*v3;
    #pragma unroll
    for (int o = 16; o; o >>= 1) {
        s  += __shfl_xor_sync(0xffffffffu, s,  o);
        sq += __shfl_xor_sync(0xffffffffu, sq, o);
    }
    float mean = s * (1.0f/DATOM);
    float var  = sq * (1.0f/DATOM) - mean*mean;
    float inv  = rsqrtf(var + 1e-5f);
    float* yr = y + (size_t)warp * DATOM;
    yr[lane]    = (v0-mean)*inv*g[lane]    + b[lane];
    yr[lane+32] = (v1-mean)*inv*g[lane+32] + b[lane+32];
    yr[lane+64] = (v2-mean)*inv*g[lane+64] + b[lane+64];
    yr[lane+96] = (v3-mean)*inv*g[lane+96] + b[lane+96];
}

// ============================================================================
// GEMM cores. 256 threads. TN=64 always. TM=64 (4x4 microtile) or TM=32 (2x4).
// ============================================================================

// ---------- fused QKVG: C[4096,512] where cols [128w : 128w+128) come from w[w] ----------
// A = g_qn [4096,128], K=128, ldc = 512 (writes straight into g_qkvg layout)
__global__ __launch_bounds__(256) void k_gemm_qkvg(
    const float* __restrict__ A,
    const float* __restrict__ w_q, const float* __restrict__ w_k,
    const float* __restrict__ w_v, const float* __restrict__ w_g,
    float* __restrict__ C) {
    __shared__ float As[16][65];
    __shared__ float Bs[16][64];
    int tid = threadIdx.x;
    int tx = tid & 15, ty = tid >> 4;
    int brow = blockIdx.y * 64;
    int bcolg = blockIdx.x * 64;                 // global col in [0,512)
    const float* B = (blockIdx.x < 2) ? ((blockIdx.x < 1) ? w_q : w_q) : w_q;
    // select weight matrix: 0..1 -> w_q, 2..3 -> w_k, 4..5 -> w_v, 6..7 -> w_g
    int wi = blockIdx.x >> 1;
    B = (wi == 0) ? w_q : (wi == 1) ? w_k : (wi == 2) ? w_v : w_g;
    int bcol = bcolg & 127;                      // col within the selected weight
    int arow = tid >> 2, ac4 = (tid & 3) << 2;
    float acc[4][4] = {};
    #pragma unroll
    for (int k0 = 0; k0 < 128; k0 += 16) {
        float4 av = *(const float4*)(A + (size_t)(brow + arow) * 128 + k0 + ac4);
        As[ac4+0][arow] = av.x; As[ac4+1][arow] = av.y;
        As[ac4+2][arow] = av.z; As[ac4+3][arow] = av.w;
        *(float4*)&Bs[ty][tx<<2] =
            *(const float4*)(B + (size_t)(k0 + ty) * 128 + bcol + (tx<<2));
        __syncthreads();
        #pragma unroll
        for (int k = 0; k < 16; k++) {
            float a[4], bb[4];
            #pragma unroll
            for (int i = 0; i < 4; i++) a[i]  = As[k][(ty<<2)+i];
            #pragma unroll
            for (int j = 0; j < 4; j++) bb[j] = Bs[k][(tx<<2)+j];
            #pragma unroll
            for (int i = 0; i < 4; i++)
                #pragma unroll
                for (int j = 0; j < 4; j++) acc[i][j] += a[i]*bb[j];
        }
        __syncthreads();
    }
    #pragma unroll
    for (int i = 0; i < 4; i++) {
        float* cr = C + (size_t)(brow + (ty<<2) + i) * 512 + bcolg + (tx<<2);
        #pragma unroll
        for (int j = 0; j < 4; j++) cr[j] = acc[i][j];
    }
}

// ---------- plain 64x64 GEMM, K=128 (token projection) ----------
__global__ __launch_bounds__(256) void k_gemm_tok(
    const float* __restrict__ A, const float* __restrict__ B, float* __restrict__ C) {
    __shared__ float As[16][65];
    __shared__ float Bs[16][64];
    int tid = threadIdx.x;
    int tx = tid & 15, ty = tid >> 4;
    int brow = blockIdx.y * 64, bcol = blockIdx.x * 64;
    int arow = tid >> 2, ac4 = (tid & 3) << 2;
    float acc[4][4] = {};
    #pragma unroll
    for (int k0 = 0; k0 < 128; k0 += 16) {
        float4 av = *(const float4*)(A + (size_t)(brow + arow) * 128 + k0 + ac4);
        As[ac4+0][arow] = av.x; As[ac4+1][arow] = av.y;
        As[ac4+2][arow] = av.z; As[ac4+3][arow] = av.w;
        *(float4*)&Bs[ty][tx<<2] =
            *(const float4*)(B + (size_t)(k0 + ty) * DMODEL + bcol + (tx<<2));
        __syncthreads();
        #pragma unroll
        for (int k = 0; k < 16; k++) {
            float a[4], bb[4];
            #pragma unroll
            for (int i = 0; i < 4; i++) a[i]  = As[k][(ty<<2)+i];
            #pragma unroll
            for (int j = 0; j < 4; j++) bb[j] = Bs[k][(tx<<2)+j];
            #pragma unroll
            for (int i = 0; i < 4; i++)
                #pragma unroll
                for (int j = 0; j < 4; j++) acc[i][j] += a[i]*bb[j];
        }
        __syncthreads();
    }
    #pragma unroll
    for (int i = 0; i < 4; i++) {
        float* cr = C + (size_t)(brow + (ty<<2) + i) * DMODEL + bcol + (tx<<2);
        #pragma unroll
        for (int j = 0; j < 4; j++) cr[j] = acc[i][j];
    }
}

// ---------- fused FFN: u = h@w1, v = h@w2, out = silu(u)*v  (64x64 tile, dual B) ----------
__global__ __launch_bounds__(256) void k_ffn12(
    const float* __restrict__ A, const float* __restrict__ B1,
    const float* __restrict__ B2, float* __restrict__ C) {
    __shared__ float As [16][65];
    __shared__ float B1s[16][64];
    __shared__ float B2s[16][64];
    int tid = threadIdx.x;
    int tx = tid & 15, ty = tid >> 4;
    int brow = blockIdx.y * 64, bcol = blockIdx.x * 64;
    int arow = tid >> 2, ac4 = (tid & 3) << 2;
    float acc1[4][4] = {}, acc2[4][4] = {};
    #pragma unroll
    for (int k0 = 0; k0 < 128; k0 += 16) {
        float4 av = *(const float4*)(A + (size_t)(brow + arow) * 128 + k0 + ac4);
        As[ac4+0][arow] = av.x; As[ac4+1][arow] = av.y;
        As[ac4+2][arow] = av.z; As[ac4+3][arow] = av.w;
        *(float4*)&B1s[ty][tx<<2] =
            *(const float4*)(B1 + (size_t)(k0 + ty) * DFF + bcol + (tx<<2));
        *(float4*)&B2s[ty][tx<<2] =
            *(const float4*)(B2 + (size_t)(k0 + ty) * DFF + bcol + (tx<<2));
        __syncthreads();
        #pragma unroll
        for (int k = 0; k < 16; k++) {
            float a[4], b1[4], b2[4];
            #pragma unroll
            for (int i = 0; i < 4; i++) a[i]  = As[k][(ty<<2)+i];
            #pragma unroll
            for (int j = 0; j < 4; j++) { b1[j] = B1s[k][(tx<<2)+j]; b2[j] = B2s[k][(tx<<2)+j]; }
            #pragma unroll
            for (int i = 0; i < 4; i++)
                #pragma unroll
                for (int j = 0; j < 4; j++) {
                    acc1[i][j] += a[i]*b1[j];
                    acc2[i][j] += a[i]*b2[j];
                }
        }
        __syncthreads();
    }
    #pragma unroll
    for (int i = 0; i < 4; i++) {
        float* cr = C + (size_t)(brow + (ty<<2) + i) * DFF + bcol + (tx<<2);
        #pragma unroll
        for (int j = 0; j < 4; j++) {
            float u = acc1[i][j];
            cr[j] = (u * d_sigmoid(u)) * acc2[i][j];
        }
    }
}

// ---------- w_o GEMM (32x64 tile) + gated-residual epilogue ----------
// q1 = c_atom + sigmoid(G) * (attout @ w_o);   N=128, K=128
__global__ __launch_bounds__(256) void k_gemm_wo(
    const float* __restrict__ A, const float* __restrict__ B,
    const float* __restrict__ c_atom) {
    __shared__ float As[16][33];
    __shared__ float Bs[16][64];
    int tid = threadIdx.x;
    int tx = tid & 15, ty = tid >> 4;
    int brow = blockIdx.y * 32, bcol = blockIdx.x * 64;
    int arow = tid >> 3, ac2 = (tid & 7) << 1;
    float acc[2][4] = {};
    #pragma unroll
    for (int k0 = 0; k0 < 128; k0 += 16) {
        float2 av = *(const float2*)(A + (size_t)(brow + arow) * 128 + k0 + ac2);
        As[ac2+0][arow] = av.x; As[ac2+1][arow] = av.y;
        *(float4*)&Bs[ty][tx<<2] =
            *(const float4*)(B + (size_t)(k0 + ty) * 128 + bcol + (tx<<2));
        __syncthreads();
        #pragma unroll
        for (int k = 0; k < 16; k++) {
            float a[2], bb[4];
            #pragma unroll
            for (int i = 0; i < 2; i++) a[i]  = As[k][(ty<<1)+i];
            #pragma unroll
            for (int j = 0; j < 4; j++) bb[j] = Bs[k][(tx<<2)+j];
            #pragma unroll
            for (int i = 0; i < 2; i++)
                #pragma unroll
                for (int j = 0; j < 4; j++) acc[i][j] += a[i]*bb[j];
        }
        __syncthreads();
    }
    #pragma unroll
    for (int i = 0; i < 2; i++) {
        int row = brow + (ty<<1) + i;
        int col0 = bcol + (tx<<2);
        const float* gr = g_qkvg + (size_t)row * 512 + 3*DATOM + col0;   // gate G
        const float* cr = c_atom + (size_t)row * 128 + col0;
        float* qr = g_q1 + (size_t)row * 128 + col0;
        #pragma unroll
        for (int j = 0; j < 4; j++)
            qr[j] = cr[j] + d_sigmoid(gr[j]) * acc[i][j];
    }
}

// ---------- w3 GEMM (32x64 tile, K=512) + residual-add epilogue: q1 += u@w3 ----------
__global__ __launch_bounds__(256) void k_gemm_w3(
    const float* __restrict__ A, const float* __restrict__ B) {
    __shared__ float As[16][33];
    __shared__ float Bs[16][64];
    int tid = threadIdx.x;
    int tx = tid & 15, ty = tid >> 4;
    int brow = blockIdx.y * 32, bcol = blockIdx.x * 64;
    int arow = tid >> 3, ac2 = (tid & 7) << 1;
    float acc[2][4] = {};
    #pragma unroll 4
    for (int k0 = 0; k0 < 512; k0 += 16) {
        float2 av = *(const float2*)(A + (size_t)(brow + arow) * DFF + k0 + ac2);
        As[ac2+0][arow] = av.x; As[ac2+1][arow] = av.y;
        *(float4*)&Bs[ty][tx<<2] =
            *(const float4*)(B + (size_t)(k0 + ty) * 128 + bcol + (tx<<2));
        __syncthreads();
        #pragma unroll
        for (int k = 0; k < 16; k++) {
            float a[2], bb[4];
            #pragma unroll
            for (int i = 0; i < 2; i++) a[i]  = As[k][(ty<<1)+i];
            #pragma unroll
            for (int j = 0; j < 4; j++) bb[j] = Bs[k][(tx<<2)+j];
            #pragma unroll
            for (int i = 0; i < 2; i++)
                #pragma unroll
                for (int j = 0; j < 4; j++) acc[i][j] += a[i]*bb[j];
        }
        __syncthreads();
    }
    #pragma unroll
    for (int i = 0; i < 2; i++) {
        float* qr = g_q1 + (size_t)(brow + (ty<<1) + i) * 128 + bcol + (tx<<2);
        #pragma unroll
        for (int j = 0; j < 4; j++) qr[j] += acc[i][j];
    }
}

// ---------------- per-atom token-group ranges (token_idx sorted per batch) ----------------
__global__ void k_groups(const int* __restrict__ tok) {
    int i = blockIdx.x * blockDim.x + threadIdx.x;
    if (i >= ROWS) return;
    int b = i / NATOM, ii = i % NATOM;
    const int* t = tok + b * NATOM;
    int v = t[ii];
    g_gs[i] = d_lower_bound(t, NATOM, v);
    g_ge[i] = d_upper_bound(t, NATOM, v);
}

// ---------------- zero only in-group bias/winner slots ----------------
__global__ void k_zero_inner() {
    int i = blockIdx.x;
    int b = i / NATOM, ii = i % NATOM;
    int s = g_gs[i], e = g_ge[i], len = e - s;
    for (int idx = threadIdx.x; idx < len * NHEAD; idx += blockDim.x) {
        int j = s + idx / NHEAD, h = idx % NHEAD;
        g_bias[(((size_t)(b*NHEAD + h) * NATOM + ii) * NATOM) + j] = 0.0f;
    }
    for (int idx = threadIdx.x; idx < len; idx += blockDim.x)
        g_winner[((size_t)(b*NATOM + ii) * NATOM) + (s + idx)] = -1;
}

// ---------------- pair scatter passes ----------------
__global__ void k_scatmax(const int* __restrict__ plmidx, const int* __restrict__ tok) {
    int gid = blockIdx.x * blockDim.x + threadIdx.x;
    if (gid >= BATCH * NPAIR) return;
    int b = gid / NPAIR, p = gid % NPAIR;
    int src = plmidx[(size_t)gid*2], dst = plmidx[(size_t)gid*2 + 1];
    if (tok[b*NATOM + src] == tok[b*NATOM + dst])
        atomicMax(&g_winner[((size_t)(b*NATOM + src) * NATOM) + dst], p);
}
__global__ void k_scatwrite(const int* __restrict__ plmidx, const int* __restrict__ tok,
                            const float* __restrict__ p_lm,
                            const float* __restrict__ pb_w, const float* __restrict__ pb_b) {
    int gid = blockIdx.x * blockDim.x + threadIdx.x;
    if (gid >= BATCH * NPAIR) return;
    int b = gid / NPAIR, p = gid % NPAIR;
    int src = plmidx[(size_t)gid*2], dst = plmidx[(size_t)gid*2 + 1];
    if (tok[b*NATOM + src] != tok[b*NATOM + dst]) return;
    if (g_winner[((size_t)(b*NATOM + src) * NATOM) + dst] != p) return;
    const float* pl = p_lm + (size_t)gid * 16;
    #pragma unroll
    for (int h = 0; h < NHEAD; h++) {
        float val = pb_b[h];
        #pragma unroll
        for (int k = 0; k < 16; k++) val += pl[k] * pb_w[k*NHEAD + h];
        g_bias[(((size_t)(b*NHEAD + h) * NATOM + src) * NATOM) + dst] = val;
    }
}

// ---------------- block-diagonal attention: 1 block/atom, 1 warp/head ----------------
__global__ void k_attn() {
    int i = blockIdx.x;
    int b = i / NATOM, ii = i % NATOM;
    int h = threadIdx.x >> 5, lane = threadIdx.x & 31;
    int s = g_gs[i], e = g_ge[i];
    const float* qrow = g_qkvg + (size_t)i * 512;
    float qd = qrow[h*DHEAD + lane];
    const float* biasrow = g_bias + ((size_t)(b*NHEAD + h) * NATOM + ii) * NATOM;
    float m = -1e30f, l = 0.0f, acc = 0.0f;
    for (int j = s; j < e; j++) {
        const float* row = g_qkvg + (size_t)(b*NATOM + j) * 512;
        float sc = qd * row[DATOM + h*DHEAD + lane];
        #pragma unroll
        for (int o = 16; o; o >>= 1) sc += __shfl_xor_sync(0xffffffffu, sc, o);
        sc = sc * 0.17677669529663687f + biasrow[j];
        float mn = fmaxf(m, sc);
        float corr = __expf(m - mn);
        float w = __expf(sc - mn);
        l = l * corr + w;
        acc = acc * corr + w * row[2*DATOM + h*DHEAD + lane];
        m = mn;
    }
    g_attout[(size_t)i * DATOM + h*DHEAD + lane] = acc / l;
}

// ---------------- token ranges + segment mean ----------------
__global__ void k_tokranges(const int* __restrict__ tok) {
    int t = blockIdx.x * blockDim.x + threadIdx.x;
    if (t >= BATCH * NTOK) return;
    int b = t / NTOK, tt = t % NTOK;
    const int* ta = tok + b * NATOM;
    int lo = d_lower_bound(ta, NATOM, tt);
    int hi = d_upper_bound(ta, NATOM, tt);
    g_ts[t] = lo; g_tc[t] = hi - lo;
}
__global__ void k_segmean(const float* __restrict__ tok_b, float* __restrict__ out) {
    int seg = blockIdx.x;
    int b = seg / NTOK;
    int d = threadIdx.x;
    int s = g_ts[seg], c = g_tc[seg];
    float sum = 0.0f;
    for (int k = 0; k < c; k++)
        sum += g_feat[(size_t)(b*NATOM + s + k) * DMODEL + d];
    out[(size_t)seg * DMODEL + d] = c ? (sum / (float)c + tok_b[d]) : 0.0f;
}

// ---------------- launch ----------------
extern "C" void kernel_launch(void* const* d_in, const int* in_sizes, int n_in,
                              void* d_out, int out_size) {
    int shift = (in_sizes[4] == 1) ? 1 : 0;
    const float* c_atom    = (const float*)d_in[0];
    const float* p_lm      = (const float*)d_in[1];
    const int*   p_lm_idx  = (const int*)  d_in[2];
    const int*   token_idx = (const int*)  d_in[3];
    const float* ln_attn_g = (const float*)d_in[4+shift];
    const float* ln_attn_b = (const float*)d_in[5+shift];
    const float* w_q       = (const float*)d_in[6+shift];
    const float* w_k       = (const float*)d_in[7+shift];
    const float* w_v       = (const float*)d_in[8+shift];
    const float* w_g       = (const float*)d_in[9+shift];
    const float* w_o       = (const float*)d_in[10+shift];
    const float* pb_w      = (const float*)d_in[11+shift];
    const float* pb_b      = (const float*)d_in[12+shift];
    const float* ln_ff_g   = (const float*)d_in[13+shift];
    const float* ln_ff_b   = (const float*)d_in[14+shift];
    const float* sw_w1     = (const float*)d_in[15+shift];
    const float* sw_w2     = (const float*)d_in[16+shift];
    const float* sw_w3     = (const float*)d_in[17+shift];
    const float* tok_w     = (const float*)d_in[18+shift];
    const float* tok_b     = (const float*)d_in[19+shift];
    float* out = (float*)d_out;

    float *p_qn, *p_qkvg, *p_attout, *p_q1, *p_h, *p_u, *p_feat;
    cudaGetSymbolAddress((void**)&p_qn,     g_qn);
    cudaGetSymbolAddress((void**)&p_qkvg,   g_qkvg);
    cudaGetSymbolAddress((void**)&p_attout, g_attout);
    cudaGetSymbolAddress((void**)&p_q1,     g_q1);
    cudaGetSymbolAddress((void**)&p_h,      g_h);
    cudaGetSymbolAddress((void**)&p_u,      g_u);
    cudaGetSymbolAddress((void**)&p_feat,   g_feat);

    // token groups + sparse bias scatter (independent of LN/GEMM chain, launch first)
    k_groups<<<ROWS/256, 256>>>(token_idx);
    k_zero_inner<<<ROWS, 128>>>();
    k_scatmax<<<(BATCH*NPAIR)/256, 256>>>(p_lm_idx, token_idx);
    k_scatwrite<<<(BATCH*NPAIR)/256, 256>>>(p_lm_idx, token_idx, p_lm, pb_w, pb_b);

    // 1. q_n = LN(c_atom)
    k_ln<<<ROWS/4, 128>>>(c_atom, ln_attn_g, ln_attn_b, p_qn);

    // 2. fused QKVG projection (one GEMM, N=512, grid=512 blocks)
    k_gemm_qkvg<<<dim3(8, ROWS/64), 256>>>(p_qn, w_q, w_k, w_v, w_g, p_qkvg);

    // 3. block-diagonal attention
    k_attn<<<ROWS, 128>>>();

    // 4. w_o projection + gated residual fused (32x64 tiles, grid=256)
    k_gemm_wo<<<dim3(2, ROWS/32), 256>>>(p_attout, w_o, c_atom);

    // 5. FFN: LN -> fused dual GEMM + SwiGLU -> w3 GEMM + residual add
    k_ln<<<ROWS/4, 128>>>(p_q1, ln_ff_g, ln_ff_b, p_h);
    k_ffn12<<<dim3(DFF/64, ROWS/64), 256>>>(p_h, sw_w1, sw_w2, p_u);
    k_gemm_w3<<<dim3(2, ROWS/32), 256>>>(p_u, sw_w3);

    // 6. token projection
    k_gemm_tok<<<dim3(DMODEL/64, ROWS/64), 256>>>(p_q1, tok_w, p_feat);

    // 7. segment mean -> output
    k_tokranges<<<(BATCH*NTOK)/256, 256>>>(token_idx);
    k_segmean<<<BATCH*NTOK, DMODEL>>>(tok_b, out);
}

// round 6
// speedup vs baseline: 1.2594x; 1.0041x over previous
#include <cuda_runtime.h>
#include <math.h>
#include <stdint.h>

// ---------------- problem constants (fixed shapes) ----------------
#define BATCH   2
#define NATOM   2048
#define DATOM   128
#define NHEAD   4
#define DHEAD   32
#define DFF     512
#define DMODEL  512
#define NPAIR   16384
#define NTOK    512
#define ROWS    (BATCH*NATOM)      // 4096

// ---------------- static device scratch (no runtime allocs) ----------------
__device__ float g_qn    [ROWS*DATOM];
__device__ float g_qkvg  [ROWS*4*DATOM];      // [Q|K|V|G] per row, stride 512
__device__ float g_attout[ROWS*DATOM];
__device__ float g_q1    [ROWS*DATOM];
__device__ float g_h     [ROWS*DATOM];
__device__ float g_u     [ROWS*DFF];          // silu(h@w1)*(h@w2) fused
__device__ float g_feat  [ROWS*DMODEL];
__device__ float g_bias  [(size_t)BATCH*NHEAD*NATOM*NATOM];  // only in-group slots touched
__device__ int   g_winner[(size_t)BATCH*NATOM*NATOM];        // only in-group slots touched
__device__ int   g_gs[ROWS], g_ge[ROWS];              // per-atom group [start,end)
__device__ int   g_ts[BATCH*NTOK], g_tc[BATCH*NTOK];  // per-token start/count

// ---------------- helpers ----------------
__device__ __forceinline__ int d_lower_bound(const int* a, int n, int v) {
    int lo = 0, hi = n;
    while (lo < hi) { int m = (lo + hi) >> 1; if (a[m] < v) lo = m + 1; else hi = m; }
    return lo;
}
__device__ __forceinline__ int d_upper_bound(const int* a, int n, int v) {
    int lo = 0, hi = n;
    while (lo < hi) { int m = (lo + hi) >> 1; if (a[m] <= v) lo = m + 1; else hi = m; }
    return lo;
}
__device__ __forceinline__ float d_sigmoid(float x) { return 1.0f / (1.0f + __expf(-x)); }

// ---------------- LayerNorm: one warp per row of 128 ----------------
__global__ void k_ln(const float* __restrict__ x, const float* __restrict__ g,
                     const float* __restrict__ b, float* __restrict__ y) {
    int warp = (blockIdx.x * blockDim.x + threadIdx.x) >> 5;
    int lane = threadIdx.x & 31;
    if (warp >= ROWS) return;
    const float* xr = x + (size_t)warp * DATOM;
    float v0 = xr[lane], v1 = xr[lane+32], v2 = xr[lane+64], v3 = xr[lane+96];
    float s  = v0+v1+v2+v3;
    float sq = v0*v0+v1*v1+v2*v2+v3*v3;
    #pragma unroll
    for (int o = 16; o; o >>= 1) {
        s  += __shfl_xor_sync(0xffffffffu, s,  o);
        sq += __shfl_xor_sync(0xffffffffu, sq, o);
    }
    float mean = s * (1.0f/DATOM);
    float var  = sq * (1.0f/DATOM) - mean*mean;
    float inv  = rsqrtf(var + 1e-5f);
    float* yr = y + (size_t)warp * DATOM;
    yr[lane]    = (v0-mean)*inv*g[lane]    + b[lane];
    yr[lane+32] = (v1-mean)*inv*g[lane+32] + b[lane+32];
    yr[lane+64] = (v2-mean)*inv*g[lane+64] + b[lane+64];
    yr[lane+96] = (v3-mean)*inv*g[lane+96] + b[lane+96];
}

// ============================================================================
// GEMM cores. 256 threads. TN=64 always. TM=64 (4x4 microtile) or TM=32 (2x4).
// ============================================================================

// ---------- fused QKVG: C[4096,512] where cols [128w : 128w+128) come from w[w] ----------
// A = g_qn [4096,128], K=128, ldc = 512 (writes straight into g_qkvg layout)
__global__ __launch_bounds__(256) void k_gemm_qkvg(
    const float* __restrict__ A,
    const float* __restrict__ w_q, const float* __restrict__ w_k,
    const float* __restrict__ w_v, const float* __restrict__ w_g,
    float* __restrict__ C) {
    __shared__ float As[16][65];
    __shared__ float Bs[16][64];
    int tid = threadIdx.x;
    int tx = tid & 15, ty = tid >> 4;
    int brow = blockIdx.y * 64;
    int bcolg = blockIdx.x * 64;                 // global col in [0,512)
    const float* B = (blockIdx.x < 2) ? ((blockIdx.x < 1) ? w_q : w_q) : w_q;
    // select weight matrix: 0..1 -> w_q, 2..3 -> w_k, 4..5 -> w_v, 6..7 -> w_g
    int wi = blockIdx.x >> 1;
    B = (wi == 0) ? w_q : (wi == 1) ? w_k : (wi == 2) ? w_v : w_g;
    int bcol = bcolg & 127;                      // col within the selected weight
    int arow = tid >> 2, ac4 = (tid & 3) << 2;
    float acc[4][4] = {};
    #pragma unroll
    for (int k0 = 0; k0 < 128; k0 += 16) {
        float4 av = *(const float4*)(A + (size_t)(brow + arow) * 128 + k0 + ac4);
        As[ac4+0][arow] = av.x; As[ac4+1][arow] = av.y;
        As[ac4+2][arow] = av.z; As[ac4+3][arow] = av.w;
        *(float4*)&Bs[ty][tx<<2] =
            *(const float4*)(B + (size_t)(k0 + ty) * 128 + bcol + (tx<<2));
        __syncthreads();
        #pragma unroll
        for (int k = 0; k < 16; k++) {
            float a[4], bb[4];
            #pragma unroll
            for (int i = 0; i < 4; i++) a[i]  = As[k][(ty<<2)+i];
            #pragma unroll
            for (int j = 0; j < 4; j++) bb[j] = Bs[k][(tx<<2)+j];
            #pragma unroll
            for (int i = 0; i < 4; i++)
                #pragma unroll
                for (int j = 0; j < 4; j++) acc[i][j] += a[i]*bb[j];
        }
        __syncthreads();
    }
    #pragma unroll
    for (int i = 0; i < 4; i++) {
        float* cr = C + (size_t)(brow + (ty<<2) + i) * 512 + bcolg + (tx<<2);
        #pragma unroll
        for (int j = 0; j < 4; j++) cr[j] = acc[i][j];
    }
}

// ---------- plain 64x64 GEMM, K=128 (token projection) ----------
__global__ __launch_bounds__(256) void k_gemm_tok(
    const float* __restrict__ A, const float* __restrict__ B, float* __restrict__ C) {
    __shared__ float As[16][65];
    __shared__ float Bs[16][64];
    int tid = threadIdx.x;
    int tx = tid & 15, ty = tid >> 4;
    int brow = blockIdx.y * 64, bcol = blockIdx.x * 64;
    int arow = tid >> 2, ac4 = (tid & 3) << 2;
    float acc[4][4] = {};
    #pragma unroll
    for (int k0 = 0; k0 < 128; k0 += 16) {
        float4 av = *(const float4*)(A + (size_t)(brow + arow) * 128 + k0 + ac4);
        As[ac4+0][arow] = av.x; As[ac4+1][arow] = av.y;
        As[ac4+2][arow] = av.z; As[ac4+3][arow] = av.w;
        *(float4*)&Bs[ty][tx<<2] =
            *(const float4*)(B + (size_t)(k0 + ty) * DMODEL + bcol + (tx<<2));
        __syncthreads();
        #pragma unroll
        for (int k = 0; k < 16; k++) {
            float a[4], bb[4];
            #pragma unroll
            for (int i = 0; i < 4; i++) a[i]  = As[k][(ty<<2)+i];
            #pragma unroll
            for (int j = 0; j < 4; j++) bb[j] = Bs[k][(tx<<2)+j];
            #pragma unroll
            for (int i = 0; i < 4; i++)
                #pragma unroll
                for (int j = 0; j < 4; j++) acc[i][j] += a[i]*bb[j];
        }
        __syncthreads();
    }
    #pragma unroll
    for (int i = 0; i < 4; i++) {
        float* cr = C + (size_t)(brow + (ty<<2) + i) * DMODEL + bcol + (tx<<2);
        #pragma unroll
        for (int j = 0; j < 4; j++) cr[j] = acc[i][j];
    }
}

// ---------- fused FFN: u = h@w1, v = h@w2, out = silu(u)*v  (64x64 tile, dual B) ----------
__global__ __launch_bounds__(256) void k_ffn12(
    const float* __restrict__ A, const float* __restrict__ B1,
    const float* __restrict__ B2, float* __restrict__ C) {
    __shared__ float As [16][65];
    __shared__ float B1s[16][64];
    __shared__ float B2s[16][64];
    int tid = threadIdx.x;
    int tx = tid & 15, ty = tid >> 4;
    int brow = blockIdx.y * 64, bcol = blockIdx.x * 64;
    int arow = tid >> 2, ac4 = (tid & 3) << 2;
    float acc1[4][4] = {}, acc2[4][4] = {};
    #pragma unroll
    for (int k0 = 0; k0 < 128; k0 += 16) {
        float4 av = *(const float4*)(A + (size_t)(brow + arow) * 128 + k0 + ac4);
        As[ac4+0][arow] = av.x; As[ac4+1][arow] = av.y;
        As[ac4+2][arow] = av.z; As[ac4+3][arow] = av.w;
        *(float4*)&B1s[ty][tx<<2] =
            *(const float4*)(B1 + (size_t)(k0 + ty) * DFF + bcol + (tx<<2));
        *(float4*)&B2s[ty][tx<<2] =
            *(const float4*)(B2 + (size_t)(k0 + ty) * DFF + bcol + (tx<<2));
        __syncthreads();
        #pragma unroll
        for (int k = 0; k < 16; k++) {
            float a[4], b1[4], b2[4];
            #pragma unroll
            for (int i = 0; i < 4; i++) a[i]  = As[k][(ty<<2)+i];
            #pragma unroll
            for (int j = 0; j < 4; j++) { b1[j] = B1s[k][(tx<<2)+j]; b2[j] = B2s[k][(tx<<2)+j]; }
            #pragma unroll
            for (int i = 0; i < 4; i++)
                #pragma unroll
                for (int j = 0; j < 4; j++) {
                    acc1[i][j] += a[i]*b1[j];
                    acc2[i][j] += a[i]*b2[j];
                }
        }
        __syncthreads();
    }
    #pragma unroll
    for (int i = 0; i < 4; i++) {
        float* cr = C + (size_t)(brow + (ty<<2) + i) * DFF + bcol + (tx<<2);
        #pragma unroll
        for (int j = 0; j < 4; j++) {
            float u = acc1[i][j];
            cr[j] = (u * d_sigmoid(u)) * acc2[i][j];
        }
    }
}

// ---------- w_o GEMM (32x64 tile) + gated-residual epilogue ----------
// q1 = c_atom + sigmoid(G) * (attout @ w_o);   N=128, K=128
__global__ __launch_bounds__(256) void k_gemm_wo(
    const float* __restrict__ A, const float* __restrict__ B,
    const float* __restrict__ c_atom) {
    __shared__ float As[16][33];
    __shared__ float Bs[16][64];
    int tid = threadIdx.x;
    int tx = tid & 15, ty = tid >> 4;
    int brow = blockIdx.y * 32, bcol = blockIdx.x * 64;
    int arow = tid >> 3, ac2 = (tid & 7) << 1;
    float acc[2][4] = {};
    #pragma unroll
    for (int k0 = 0; k0 < 128; k0 += 16) {
        float2 av = *(const float2*)(A + (size_t)(brow + arow) * 128 + k0 + ac2);
        As[ac2+0][arow] = av.x; As[ac2+1][arow] = av.y;
        *(float4*)&Bs[ty][tx<<2] =
            *(const float4*)(B + (size_t)(k0 + ty) * 128 + bcol + (tx<<2));
        __syncthreads();
        #pragma unroll
        for (int k = 0; k < 16; k++) {
            float a[2], bb[4];
            #pragma unroll
            for (int i = 0; i < 2; i++) a[i]  = As[k][(ty<<1)+i];
            #pragma unroll
            for (int j = 0; j < 4; j++) bb[j] = Bs[k][(tx<<2)+j];
            #pragma unroll
            for (int i = 0; i < 2; i++)
                #pragma unroll
                for (int j = 0; j < 4; j++) acc[i][j] += a[i]*bb[j];
        }
        __syncthreads();
    }
    #pragma unroll
    for (int i = 0; i < 2; i++) {
        int row = brow + (ty<<1) + i;
        int col0 = bcol + (tx<<2);
        const float* gr = g_qkvg + (size_t)row * 512 + 3*DATOM + col0;   // gate G
        const float* cr = c_atom + (size_t)row * 128 + col0;
        float* qr = g_q1 + (size_t)row * 128 + col0;
        #pragma unroll
        for (int j = 0; j < 4; j++)
            qr[j] = cr[j] + d_sigmoid(gr[j]) * acc[i][j];
    }
}

// ---------- w3 GEMM (32x64 tile, K=512) + residual-add epilogue: q1 += u@w3 ----------
__global__ __launch_bounds__(256) void k_gemm_w3(
    const float* __restrict__ A, const float* __restrict__ B) {
    __shared__ float As[16][33];
    __shared__ float Bs[16][64];
    int tid = threadIdx.x;
    int tx = tid & 15, ty = tid >> 4;
    int brow = blockIdx.y * 32, bcol = blockIdx.x * 64;
    int arow = tid >> 3, ac2 = (tid & 7) << 1;
    float acc[2][4] = {};
    #pragma unroll 4
    for (int k0 = 0; k0 < 512; k0 += 16) {
        float2 av = *(const float2*)(A + (size_t)(brow + arow) * DFF + k0 + ac2);
        As[ac2+0][arow] = av.x; As[ac2+1][arow] = av.y;
        *(float4*)&Bs[ty][tx<<2] =
            *(const float4*)(B + (size_t)(k0 + ty) * 128 + bcol + (tx<<2));
        __syncthreads();
        #pragma unroll
        for (int k = 0; k < 16; k++) {
            float a[2], bb[4];
            #pragma unroll
            for (int i = 0; i < 2; i++) a[i]  = As[k][(ty<<1)+i];
            #pragma unroll
            for (int j = 0; j < 4; j++) bb[j] = Bs[k][(tx<<2)+j];
            #pragma unroll
            for (int i = 0; i < 2; i++)
                #pragma unroll
                for (int j = 0; j < 4; j++) acc[i][j] += a[i]*bb[j];
        }
        __syncthreads();
    }
    #pragma unroll
    for (int i = 0; i < 2; i++) {
        float* qr = g_q1 + (size_t)(brow + (ty<<1) + i) * 128 + bcol + (tx<<2);
        #pragma unroll
        for (int j = 0; j < 4; j++) qr[j] += acc[i][j];
    }
}

// ---------------- per-atom token-group ranges (token_idx sorted per batch) ----------------
__global__ void k_groups(const int* __restrict__ tok) {
    int i = blockIdx.x * blockDim.x + threadIdx.x;
    if (i >= ROWS) return;
    int b = i / NATOM, ii = i % NATOM;
    const int* t = tok + b * NATOM;
    int v = t[ii];
    g_gs[i] = d_lower_bound(t, NATOM, v);
    g_ge[i] = d_upper_bound(t, NATOM, v);
}

// ---------------- zero only in-group bias/winner slots ----------------
__global__ void k_zero_inner() {
    int i = blockIdx.x;
    int b = i / NATOM, ii = i % NATOM;
    int s = g_gs[i], e = g_ge[i], len = e - s;
    for (int idx = threadIdx.x; idx < len * NHEAD; idx += blockDim.x) {
        int j = s + idx / NHEAD, h = idx % NHEAD;
        g_bias[(((size_t)(b*NHEAD + h) * NATOM + ii) * NATOM) + j] = 0.0f;
    }
    for (int idx = threadIdx.x; idx < len; idx += blockDim.x)
        g_winner[((size_t)(b*NATOM + ii) * NATOM) + (s + idx)] = -1;
}

// ---------------- pair scatter passes ----------------
__global__ void k_scatmax(const int* __restrict__ plmidx, const int* __restrict__ tok) {
    int gid = blockIdx.x * blockDim.x + threadIdx.x;
    if (gid >= BATCH * NPAIR) return;
    int b = gid / NPAIR, p = gid % NPAIR;
    int src = plmidx[(size_t)gid*2], dst = plmidx[(size_t)gid*2 + 1];
    if (tok[b*NATOM + src] == tok[b*NATOM + dst])
        atomicMax(&g_winner[((size_t)(b*NATOM + src) * NATOM) + dst], p);
}
__global__ void k_scatwrite(const int* __restrict__ plmidx, const int* __restrict__ tok,
                            const float* __restrict__ p_lm,
                            const float* __restrict__ pb_w, const float* __restrict__ pb_b) {
    int gid = blockIdx.x * blockDim.x + threadIdx.x;
    if (gid >= BATCH * NPAIR) return;
    int b = gid / NPAIR, p = gid % NPAIR;
    int src = plmidx[(size_t)gid*2], dst = plmidx[(size_t)gid*2 + 1];
    if (tok[b*NATOM + src] != tok[b*NATOM + dst]) return;
    if (g_winner[((size_t)(b*NATOM + src) * NATOM) + dst] != p) return;
    const float* pl = p_lm + (size_t)gid * 16;
    #pragma unroll
    for (int h = 0; h < NHEAD; h++) {
        float val = pb_b[h];
        #pragma unroll
        for (int k = 0; k < 16; k++) val += pl[k] * pb_w[k*NHEAD + h];
        g_bias[(((size_t)(b*NHEAD + h) * NATOM + src) * NATOM) + dst] = val;
    }
}

// ---------------- block-diagonal attention: 1 block/atom, 1 warp/head ----------------
__global__ void k_attn() {
    int i = blockIdx.x;
    int b = i / NATOM, ii = i % NATOM;
    int h = threadIdx.x >> 5, lane = threadIdx.x & 31;
    int s = g_gs[i], e = g_ge[i];
    const float* qrow = g_qkvg + (size_t)i * 512;
    float qd = qrow[h*DHEAD + lane];
    const float* biasrow = g_bias + ((size_t)(b*NHEAD + h) * NATOM + ii) * NATOM;
    float m = -1e30f, l = 0.0f, acc = 0.0f;
    for (int j = s; j < e; j++) {
        const float* row = g_qkvg + (size_t)(b*NATOM + j) * 512;
        float sc = qd * row[DATOM + h*DHEAD + lane];
        #pragma unroll
        for (int o = 16; o; o >>= 1) sc += __shfl_xor_sync(0xffffffffu, sc, o);
        sc = sc * 0.17677669529663687f + biasrow[j];
        float mn = fmaxf(m, sc);
        float corr = __expf(m - mn);
        float w = __expf(sc - mn);
        l = l * corr + w;
        acc = acc * corr + w * row[2*DATOM + h*DHEAD + lane];
        m = mn;
    }
    g_attout[(size_t)i * DATOM + h*DHEAD + lane] = acc / l;
}

// ---------------- token ranges + segment mean ----------------
__global__ void k_tokranges(const int* __restrict__ tok) {
    int t = blockIdx.x * blockDim.x + threadIdx.x;
    if (t >= BATCH * NTOK) return;
    int b = t / NTOK, tt = t % NTOK;
    const int* ta = tok + b * NATOM;
    int lo = d_lower_bound(ta, NATOM, tt);
    int hi = d_upper_bound(ta, NATOM, tt);
    g_ts[t] = lo; g_tc[t] = hi - lo;
}
__global__ void k_segmean(const float* __restrict__ tok_b, float* __restrict__ out) {
    int seg = blockIdx.x;
    int b = seg / NTOK;
    int d = threadIdx.x;
    int s = g_ts[seg], c = g_tc[seg];
    float sum = 0.0f;
    for (int k = 0; k < c; k++)
        sum += g_feat[(size_t)(b*NATOM + s + k) * DMODEL + d];
    out[(size_t)seg * DMODEL + d] = c ? (sum / (float)c + tok_b[d]) : 0.0f;
}

// ---------------- launch ----------------
extern "C" void kernel_launch(void* const* d_in, const int* in_sizes, int n_in,
                              void* d_out, int out_size) {
    int shift = (in_sizes[4] == 1) ? 1 : 0;
    const float* c_atom    = (const float*)d_in[0];
    const float* p_lm      = (const float*)d_in[1];
    const int*   p_lm_idx  = (const int*)  d_in[2];
    const int*   token_idx = (const int*)  d_in[3];
    const float* ln_attn_g = (const float*)d_in[4+shift];
    const float* ln_attn_b = (const float*)d_in[5+shift];
    const float* w_q       = (const float*)d_in[6+shift];
    const float* w_k       = (const float*)d_in[7+shift];
    const float* w_v       = (const float*)d_in[8+shift];
    const float* w_g       = (const float*)d_in[9+shift];
    const float* w_o       = (const float*)d_in[10+shift];
    const float* pb_w      = (const float*)d_in[11+shift];
    const float* pb_b      = (const float*)d_in[12+shift];
    const float* ln_ff_g   = (const float*)d_in[13+shift];
    const float* ln_ff_b   = (const float*)d_in[14+shift];
    const float* sw_w1     = (const float*)d_in[15+shift];
    const float* sw_w2     = (const float*)d_in[16+shift];
    const float* sw_w3     = (const float*)d_in[17+shift];
    const float* tok_w     = (const float*)d_in[18+shift];
    const float* tok_b     = (const float*)d_in[19+shift];
    float* out = (float*)d_out;

    float *p_qn, *p_qkvg, *p_attout, *p_q1, *p_h, *p_u, *p_feat;
    cudaGetSymbolAddress((void**)&p_qn,     g_qn);
    cudaGetSymbolAddress((void**)&p_qkvg,   g_qkvg);
    cudaGetSymbolAddress((void**)&p_attout, g_attout);
    cudaGetSymbolAddress((void**)&p_q1,     g_q1);
    cudaGetSymbolAddress((void**)&p_h,      g_h);
    cudaGetSymbolAddress((void**)&p_u,      g_u);
    cudaGetSymbolAddress((void**)&p_feat,   g_feat);

    // token groups + sparse bias scatter (independent of LN/GEMM chain, launch first)
    k_groups<<<ROWS/256, 256>>>(token_idx);
    k_zero_inner<<<ROWS, 128>>>();
    k_scatmax<<<(BATCH*NPAIR)/256, 256>>>(p_lm_idx, token_idx);
    k_scatwrite<<<(BATCH*NPAIR)/256, 256>>>(p_lm_idx, token_idx, p_lm, pb_w, pb_b);

    // 1. q_n = LN(c_atom)
    k_ln<<<ROWS/4, 128>>>(c_atom, ln_attn_g, ln_attn_b, p_qn);

    // 2. fused QKVG projection (one GEMM, N=512, grid=512 blocks)
    k_gemm_qkvg<<<dim3(8, ROWS/64), 256>>>(p_qn, w_q, w_k, w_v, w_g, p_qkvg);

    // 3. block-diagonal attention
    k_attn<<<ROWS, 128>>>();

    // 4. w_o projection + gated residual fused (32x64 tiles, grid=256)
    k_gemm_wo<<<dim3(2, ROWS/32), 256>>>(p_attout, w_o, c_atom);

    // 5. FFN: LN -> fused dual GEMM + SwiGLU -> w3 GEMM + residual add
    k_ln<<<ROWS/4, 128>>>(p_q1, ln_ff_g, ln_ff_b, p_h);
    k_ffn12<<<dim3(DFF/64, ROWS/64), 256>>>(p_h, sw_w1, sw_w2, p_u);
    k_gemm_w3<<<dim3(2, ROWS/32), 256>>>(p_u, sw_w3);

    // 6. token projection
    k_gemm_tok<<<dim3(DMODEL/64, ROWS/64), 256>>>(p_q1, tok_w, p_feat);

    // 7. segment mean -> output
    k_tokranges<<<(BATCH*NTOK)/256, 256>>>(token_idx);
    k_segmean<<<BATCH*NTOK, DMODEL>>>(tok_b, out);
}

// round 7
// speedup vs baseline: 1.3929x; 1.1059x over previous
#include <cuda_runtime.h>
#include <cuda_bf16.h>
#include <math.h>
#include <stdint.h>

// ---------------- problem constants (fixed shapes) ----------------
#define BATCH   2
#define NATOM   2048
#define DATOM   128
#define NHEAD   4
#define DHEAD   32
#define DFF     512
#define DMODEL  512
#define NPAIR   16384
#define NTOK    512
#define ROWS    (BATCH*NATOM)      // 4096
#define MAXG    96                 // max atoms per token group (avg ~4-5; 96 is astronomically safe)

// ---------------- static device scratch ----------------
__device__ float g_qn    [ROWS*DATOM];
__device__ float g_qkvg  [ROWS*4*DATOM];      // [Q|K|V|G] per row, stride 512
__device__ float g_attout[ROWS*DATOM];
__device__ float g_q1    [ROWS*DATOM];
__device__ float g_h     [ROWS*DATOM];
__device__ float g_u     [ROWS*DFF];
__device__ float g_feat  [ROWS*DMODEL];
__device__ __align__(16) float g_biasc[(size_t)ROWS*MAXG*NHEAD];  // compact in-group bias
__device__ __align__(16) int   g_winc [(size_t)ROWS*MAXG];        // last-write-wins winner
__device__ int   g_gs[ROWS], g_ge[ROWS];
__device__ int   g_ts[BATCH*NTOK], g_tc[BATCH*NTOK];

// ---------------- helpers ----------------
__device__ __forceinline__ int d_lower_bound(const int* a, int n, int v) {
    int lo = 0, hi = n;
    while (lo < hi) { int m = (lo + hi) >> 1; if (a[m] < v) lo = m + 1; else hi = m; }
    return lo;
}
__device__ __forceinline__ int d_upper_bound(const int* a, int n, int v) {
    int lo = 0, hi = n;
    while (lo < hi) { int m = (lo + hi) >> 1; if (a[m] <= v) lo = m + 1; else hi = m; }
    return lo;
}
__device__ __forceinline__ float d_sigmoid(float x) { return 1.0f / (1.0f + __expf(-x)); }

__device__ __forceinline__ void mma_bf16(float d[4], const uint32_t a[4], const uint32_t b[2]) {
    asm volatile(
        "mma.sync.aligned.m16n8k16.row.col.f32.bf16.bf16.f32 "
        "{%0,%1,%2,%3}, {%4,%5,%6,%7}, {%8,%9}, {%0,%1,%2,%3};\n"
        : "+f"(d[0]), "+f"(d[1]), "+f"(d[2]), "+f"(d[3])
        : "r"(a[0]), "r"(a[1]), "r"(a[2]), "r"(a[3]), "r"(b[0]), "r"(b[1]));
}
// split fp32 -> (hi bf16, lo bf16 of residual)
__device__ __forceinline__ void cvt_hl(float x, unsigned short& h, unsigned short& l) {
    __nv_bfloat16 hb = __float2bfloat16(x);
    float r = x - __bfloat162float(hb);
    h = __bfloat16_as_ushort(hb);
    l = __bfloat16_as_ushort(__float2bfloat16(r));
}

// ---------------- LayerNorm: one warp per row of 128 ----------------
__global__ void k_ln(const float* __restrict__ x, const float* __restrict__ g,
                     const float* __restrict__ b, float* __restrict__ y) {
    int warp = (blockIdx.x * blockDim.x + threadIdx.x) >> 5;
    int lane = threadIdx.x & 31;
    if (warp >= ROWS) return;
    const float* xr = x + (size_t)warp * DATOM;
    float v0 = xr[lane], v1 = xr[lane+32], v2 = xr[lane+64], v3 = xr[lane+96];
    float s  = v0+v1+v2+v3;
    float sq = v0*v0+v1*v1+v2*v2+v3*v3;
    #pragma unroll
    for (int o = 16; o; o >>= 1) {
        s  += __shfl_xor_sync(0xffffffffu, s,  o);
        sq += __shfl_xor_sync(0xffffffffu, sq, o);
    }
    float mean = s * (1.0f/DATOM);
    float var  = sq * (1.0f/DATOM) - mean*mean;
    float inv  = rsqrtf(var + 1e-5f);
    float* yr = y + (size_t)warp * DATOM;
    yr[lane]    = (v0-mean)*inv*g[lane]    + b[lane];
    yr[lane+32] = (v1-mean)*inv*g[lane+32] + b[lane+32];
    yr[lane+64] = (v2-mean)*inv*g[lane+64] + b[lane+64];
    yr[lane+96] = (v3-mean)*inv*g[lane+96] + b[lane+96];
}

// ============================================================================
// Split-bf16 tensor-core GEMM. C = A(f32)@B(f32) computed as AhBh+AhBl+AlBh.
// Block tile BM x 64, 256 threads. BM=128: warps 4x2 (warp tile 32x32);
// BM=64: warps 2x4 (warp tile 32x16). K-chunk = 16 (one mma k-step).
// EPI: 0 = store C[r*ldc+c]
//      1 = qkvg (B selected from 4 weights by blockIdx.x>>1, store ldc)
//      2 = wo  (g_q1 = aux + sigmoid(G)*acc)
//      4 = w3  (g_q1 += acc)
// ============================================================================
template<int BM, int KDIM, int EPI>
__global__ __launch_bounds__(256) void k_mma(
    const float* __restrict__ A, int lda,
    const float* __restrict__ B0, const float* __restrict__ B1t,
    const float* __restrict__ B2t, const float* __restrict__ B3t,
    int ldb, float* __restrict__ C, int ldc,
    const float* __restrict__ aux) {
    constexpr int WR  = (BM == 128) ? 4 : 2;
    constexpr int WC  = 8 / WR;
    constexpr int WTM = BM / WR;          // 32
    constexpr int WTN = 64 / WC;          // 32 or 16
    constexpr int MT  = WTM / 16;         // 2
    constexpr int NT  = WTN / 8;          // 4 or 2
    constexpr int PAD = 24;
    constexpr int AQ  = BM / 64;          // float4 loads of A per thread per chunk

    __shared__ __nv_bfloat16 Ah[BM][PAD], Al[BM][PAD];
    __shared__ __nv_bfloat16 Bh[64][PAD], Bl[64][PAD];

    int tid  = threadIdx.x;
    int warp = tid >> 5, lane = tid & 31;
    int wm = warp % WR, wn = warp / WR;
    int gq = lane >> 2, t4 = lane & 3;

    int bm = blockIdx.y * BM;
    const float* Bsel;
    int bn;                                  // col base inside selected B
    if (EPI == 1) {
        int wi = blockIdx.x >> 1;
        Bsel = (wi == 0) ? B0 : (wi == 1) ? B1t : (wi == 2) ? B2t : B3t;
        bn = (blockIdx.x & 1) * 64;
    } else { Bsel = B0; bn = blockIdx.x * 64; }
    int cn = blockIdx.x * 64;                // global output col base

    float acc[MT][NT][4];
    #pragma unroll
    for (int i = 0; i < MT; i++)
        #pragma unroll
        for (int j = 0; j < NT; j++)
            #pragma unroll
            for (int q = 0; q < 4; q++) acc[i][j][q] = 0.0f;

    for (int kc = 0; kc < KDIM; kc += 16) {
        // ---- load A tile (BM x 16 fp32), split, store to smem ----
        float4 av[AQ]; int arow[AQ], acol[AQ];
        #pragma unroll
        for (int q = 0; q < AQ; q++) {
            int slot = tid * AQ + q;
            arow[q] = slot >> 2;
            acol[q] = (slot & 3) << 2;
            av[q] = *(const float4*)(A + (size_t)(bm + arow[q]) * lda + kc + acol[q]);
        }
        // ---- load B tile (16 x 64 fp32) ----
        int bk = tid >> 4, bnn = (tid & 15) << 2;
        float4 bv = *(const float4*)(Bsel + (size_t)(kc + bk) * ldb + bn + bnn);

        #pragma unroll
        for (int q = 0; q < AQ; q++) {
            unsigned short h0,l0,h1,l1,h2,l2,h3,l3;
            cvt_hl(av[q].x,h0,l0); cvt_hl(av[q].y,h1,l1);
            cvt_hl(av[q].z,h2,l2); cvt_hl(av[q].w,h3,l3);
            *(uint32_t*)&Ah[arow[q]][acol[q]  ] = (uint32_t)h0 | ((uint32_t)h1 << 16);
            *(uint32_t*)&Ah[arow[q]][acol[q]+2] = (uint32_t)h2 | ((uint32_t)h3 << 16);
            *(uint32_t*)&Al[arow[q]][acol[q]  ] = (uint32_t)l0 | ((uint32_t)l1 << 16);
            *(uint32_t*)&Al[arow[q]][acol[q]+2] = (uint32_t)l2 | ((uint32_t)l3 << 16);
        }
        {
            float e[4] = {bv.x, bv.y, bv.z, bv.w};
            #pragma unroll
            for (int j = 0; j < 4; j++) {
                __nv_bfloat16 hb = __float2bfloat16(e[j]);
                Bh[bnn + j][bk] = hb;
                Bl[bnn + j][bk] = __float2bfloat16(e[j] - __bfloat162float(hb));
            }
        }
        __syncthreads();

        // ---- fragments ----
        uint32_t afh[MT][4], afl[MT][4], bfh[NT][2], bfl[NT][2];
        #pragma unroll
        for (int mt = 0; mt < MT; mt++) {
            int r0 = wm * WTM + mt * 16 + gq;
            afh[mt][0] = *(const uint32_t*)&Ah[r0    ][2*t4  ];
            afh[mt][1] = *(const uint32_t*)&Ah[r0 + 8][2*t4  ];
            afh[mt][2] = *(const uint32_t*)&Ah[r0    ][2*t4+8];
            afh[mt][3] = *(const uint32_t*)&Ah[r0 + 8][2*t4+8];
            afl[mt][0] = *(const uint32_t*)&Al[r0    ][2*t4  ];
            afl[mt][1] = *(const uint32_t*)&Al[r0 + 8][2*t4  ];
            afl[mt][2] = *(const uint32_t*)&Al[r0    ][2*t4+8];
            afl[mt][3] = *(const uint32_t*)&Al[r0 + 8][2*t4+8];
        }
        #pragma unroll
        for (int nt = 0; nt < NT; nt++) {
            int c0 = wn * WTN + nt * 8 + gq;
            bfh[nt][0] = *(const uint32_t*)&Bh[c0][2*t4  ];
            bfh[nt][1] = *(const uint32_t*)&Bh[c0][2*t4+8];
            bfl[nt][0] = *(const uint32_t*)&Bl[c0][2*t4  ];
            bfl[nt][1] = *(const uint32_t*)&Bl[c0][2*t4+8];
        }
        #pragma unroll
        for (int mt = 0; mt < MT; mt++)
            #pragma unroll
            for (int nt = 0; nt < NT; nt++) {
                mma_bf16(acc[mt][nt], afh[mt], bfh[nt]);
                mma_bf16(acc[mt][nt], afh[mt], bfl[nt]);
                mma_bf16(acc[mt][nt], afl[mt], bfh[nt]);
            }
        __syncthreads();
    }

    // ---- epilogue ----
    #pragma unroll
    for (int mt = 0; mt < MT; mt++)
        #pragma unroll
        for (int nt = 0; nt < NT; nt++)
            #pragma unroll
            for (int ci = 0; ci < 4; ci++) {
                int r = bm + wm * WTM + mt * 16 + gq + ((ci >> 1) ? 8 : 0);
                int c = cn + wn * WTN + nt * 8 + 2 * t4 + (ci & 1);
                float v = acc[mt][nt][ci];
                if constexpr (EPI == 0 || EPI == 1) {
                    C[(size_t)r * ldc + c] = v;
                } else if constexpr (EPI == 2) {
                    float gt = g_qkvg[(size_t)r * 512 + 3*DATOM + c];
                    g_q1[(size_t)r * DATOM + c] =
                        aux[(size_t)r * DATOM + c] + d_sigmoid(gt) * v;
                } else if constexpr (EPI == 4) {
                    g_q1[(size_t)r * DATOM + c] += v;
                }
            }
}

// ---------- dual-B FFN MMA: g_u = silu(h@w1) * (h@w2), BM=128, K=128 ----------
__global__ __launch_bounds__(256) void k_mma_ffn(
    const float* __restrict__ A,
    const float* __restrict__ W1, const float* __restrict__ W2) {
    constexpr int PAD = 24;
    __shared__ __nv_bfloat16 Ah[128][PAD], Al[128][PAD];
    __shared__ __nv_bfloat16 B1h[64][PAD], B1l[64][PAD];
    __shared__ __nv_bfloat16 B2h[64][PAD], B2l[64][PAD];

    int tid  = threadIdx.x;
    int warp = tid >> 5, lane = tid & 31;
    int wm = warp & 3, wn = warp >> 2;          // 4x2 warps, tile 32x32
    int gq = lane >> 2, t4 = lane & 3;
    int bm = blockIdx.y * 128;
    int bn = blockIdx.x * 64;

    float au[2][4][4] = {}, avv[2][4][4] = {};

    for (int kc = 0; kc < 128; kc += 16) {
        float4 a0 = *(const float4*)(A + (size_t)(bm + (tid >> 1)) * 128 + kc + ((tid & 1) << 3));
        float4 a1 = *(const float4*)(A + (size_t)(bm + (tid >> 1)) * 128 + kc + ((tid & 1) << 3) + 4);
        int bk = tid >> 4, bnn = (tid & 15) << 2;
        float4 b1 = *(const float4*)(W1 + (size_t)(kc + bk) * DFF + bn + bnn);
        float4 b2 = *(const float4*)(W2 + (size_t)(kc + bk) * DFF + bn + bnn);

        int row = tid >> 1, col = (tid & 1) << 3;
        float ea[8] = {a0.x,a0.y,a0.z,a0.w,a1.x,a1.y,a1.z,a1.w};
        #pragma unroll
        for (int p = 0; p < 4; p++) {
            unsigned short h0,l0,h1,l1;
            cvt_hl(ea[2*p],h0,l0); cvt_hl(ea[2*p+1],h1,l1);
            *(uint32_t*)&Ah[row][col + 2*p] = (uint32_t)h0 | ((uint32_t)h1 << 16);
            *(uint32_t*)&Al[row][col + 2*p] = (uint32_t)l0 | ((uint32_t)l1 << 16);
        }
        float e1[4] = {b1.x,b1.y,b1.z,b1.w}, e2[4] = {b2.x,b2.y,b2.z,b2.w};
        #pragma unroll
        for (int j = 0; j < 4; j++) {
            __nv_bfloat16 hb = __float2bfloat16(e1[j]);
            B1h[bnn+j][bk] = hb;
            B1l[bnn+j][bk] = __float2bfloat16(e1[j] - __bfloat162float(hb));
            __nv_bfloat16 hb2 = __float2bfloat16(e2[j]);
            B2h[bnn+j][bk] = hb2;
            B2l[bnn+j][bk] = __float2bfloat16(e2[j] - __bfloat162float(hb2));
        }
        __syncthreads();

        uint32_t afh[2][4], afl[2][4];
        #pragma unroll
        for (int mt = 0; mt < 2; mt++) {
            int r0 = wm * 32 + mt * 16 + gq;
            afh[mt][0] = *(const uint32_t*)&Ah[r0  ][2*t4  ];
            afh[mt][1] = *(const uint32_t*)&Ah[r0+8][2*t4  ];
            afh[mt][2] = *(const uint32_t*)&Ah[r0  ][2*t4+8];
            afh[mt][3] = *(const uint32_t*)&Ah[r0+8][2*t4+8];
            afl[mt][0] = *(const uint32_t*)&Al[r0  ][2*t4  ];
            afl[mt][1] = *(const uint32_t*)&Al[r0+8][2*t4  ];
            afl[mt][2] = *(const uint32_t*)&Al[r0  ][2*t4+8];
            afl[mt][3] = *(const uint32_t*)&Al[r0+8][2*t4+8];
        }
        #pragma unroll
        for (int nt = 0; nt < 4; nt++) {
            int c0 = wn * 32 + nt * 8 + gq;
            uint32_t b1f[2] = {*(const uint32_t*)&B1h[c0][2*t4], *(const uint32_t*)&B1h[c0][2*t4+8]};
            uint32_t b1g[2] = {*(const uint32_t*)&B1l[c0][2*t4], *(const uint32_t*)&B1l[c0][2*t4+8]};
            uint32_t b2f[2] = {*(const uint32_t*)&B2h[c0][2*t4], *(const uint32_t*)&B2h[c0][2*t4+8]};
            uint32_t b2g[2] = {*(const uint32_t*)&B2l[c0][2*t4], *(const uint32_t*)&B2l[c0][2*t4+8]};
            #pragma unroll
            for (int mt = 0; mt < 2; mt++) {
                mma_bf16(au [mt][nt], afh[mt], b1f);
                mma_bf16(au [mt][nt], afh[mt], b1g);
                mma_bf16(au [mt][nt], afl[mt], b1f);
                mma_bf16(avv[mt][nt], afh[mt], b2f);
                mma_bf16(avv[mt][nt], afh[mt], b2g);
                mma_bf16(avv[mt][nt], afl[mt], b2f);
            }
        }
        __syncthreads();
    }
    #pragma unroll
    for (int mt = 0; mt < 2; mt++)
        #pragma unroll
        for (int nt = 0; nt < 4; nt++)
            #pragma unroll
            for (int ci = 0; ci < 4; ci++) {
                int r = bm + wm * 32 + mt * 16 + gq + ((ci >> 1) ? 8 : 0);
                int c = bn + wn * 32 + nt * 8 + 2 * t4 + (ci & 1);
                float uu = au[mt][nt][ci];
                g_u[(size_t)r * DFF + c] = (uu * d_sigmoid(uu)) * avv[mt][nt][ci];
            }
}

// ---------------- per-atom token-group ranges ----------------
__global__ void k_groups(const int* __restrict__ tok) {
    int i = blockIdx.x * blockDim.x + threadIdx.x;
    if (i >= ROWS) return;
    int b = i / NATOM, ii = i % NATOM;
    const int* t = tok + b * NATOM;
    int v = t[ii];
    g_gs[i] = d_lower_bound(t, NATOM, v);
    g_ge[i] = d_upper_bound(t, NATOM, v);
}

// ---------------- zero compact bias + winner (streaming) ----------------
__global__ void k_zeroc() {
    int idx = blockIdx.x * blockDim.x + threadIdx.x;
    if (idx < ROWS * MAXG)               // float4 granularity over bias (NHEAD=4 floats/slot)
        ((float4*)g_biasc)[idx] = make_float4(0.f, 0.f, 0.f, 0.f);
    if (idx < ROWS * MAXG / 4)
        ((int4*)g_winc)[idx] = make_int4(-1, -1, -1, -1);
}

// ---------------- pair scatter passes (compact slots) ----------------
__global__ void k_scatmax(const int* __restrict__ plmidx, const int* __restrict__ tok) {
    int gid = blockIdx.x * blockDim.x + threadIdx.x;
    if (gid >= BATCH * NPAIR) return;
    int b = gid / NPAIR, p = gid % NPAIR;
    int src = plmidx[(size_t)gid*2], dst = plmidx[(size_t)gid*2 + 1];
    if (tok[b*NATOM + src] != tok[b*NATOM + dst]) return;
    int i = b*NATOM + src;
    int slot = dst - g_gs[i];
    if (slot >= 0 && slot < MAXG)
        atomicMax(&g_winc[(size_t)i * MAXG + slot], p);
}
__global__ void k_scatwrite(const int* __restrict__ plmidx, const int* __restrict__ tok,
                            const float* __restrict__ p_lm,
                            const float* __restrict__ pb_w, const float* __restrict__ pb_b) {
    int gid = blockIdx.x * blockDim.x + threadIdx.x;
    if (gid >= BATCH * NPAIR) return;
    int b = gid / NPAIR, p = gid % NPAIR;
    int src = plmidx[(size_t)gid*2], dst = plmidx[(size_t)gid*2 + 1];
    if (tok[b*NATOM + src] != tok[b*NATOM + dst]) return;
    int i = b*NATOM + src;
    int slot = dst - g_gs[i];
    if (slot < 0 || slot >= MAXG) return;
    if (g_winc[(size_t)i * MAXG + slot] != p) return;
    const float* pl = p_lm + (size_t)gid * 16;
    #pragma unroll
    for (int h = 0; h < NHEAD; h++) {
        float val = pb_b[h];
        #pragma unroll
        for (int k = 0; k < 16; k++) val += pl[k] * pb_w[k*NHEAD + h];
        g_biasc[((size_t)i * MAXG + slot) * NHEAD + h] = val;
    }
}

// ---------------- block-diagonal attention: 1 block/atom, 1 warp/head ----------------
__global__ void k_attn() {
    int i = blockIdx.x;
    int b = i / NATOM;
    int h = threadIdx.x >> 5, lane = threadIdx.x & 31;
    int s = g_gs[i], e = g_ge[i];
    const float* qrow = g_qkvg + (size_t)i * 512;
    float qd = qrow[h*DHEAD + lane];
    const float* biasrow = g_biasc + (size_t)i * MAXG * NHEAD + h;
    float m = -1e30f, l = 0.0f, acc = 0.0f;
    for (int j = s; j < e; j++) {
        const float* row = g_qkvg + (size_t)(b*NATOM + j) * 512;
        float sc = qd * row[DATOM + h*DHEAD + lane];
        #pragma unroll
        for (int o = 16; o; o >>= 1) sc += __shfl_xor_sync(0xffffffffu, sc, o);
        int slot = j - s;
        float bias = (slot < MAXG) ? biasrow[(size_t)slot * NHEAD] : 0.0f;
        sc = sc * 0.17677669529663687f + bias;
        float mn = fmaxf(m, sc);
        float corr = __expf(m - mn);
        float w = __expf(sc - mn);
        l = l * corr + w;
        acc = acc * corr + w * row[2*DATOM + h*DHEAD + lane];
        m = mn;
    }
    g_attout[(size_t)i * DATOM + h*DHEAD + lane] = acc / l;
}

// ---------------- token ranges + segment mean ----------------
__global__ void k_tokranges(const int* __restrict__ tok) {
    int t = blockIdx.x * blockDim.x + threadIdx.x;
    if (t >= BATCH * NTOK) return;
    int b = t / NTOK, tt = t % NTOK;
    const int* ta = tok + b * NATOM;
    int lo = d_lower_bound(ta, NATOM, tt);
    int hi = d_upper_bound(ta, NATOM, tt);
    g_ts[t] = lo; g_tc[t] = hi - lo;
}
__global__ void k_segmean(const float* __restrict__ tok_b, float* __restrict__ out) {
    int seg = blockIdx.x;
    int b = seg / NTOK;
    int d = threadIdx.x;
    int s = g_ts[seg], c = g_tc[seg];
    float sum = 0.0f;
    for (int k = 0; k < c; k++)
        sum += g_feat[(size_t)(b*NATOM + s + k) * DMODEL + d];
    out[(size_t)seg * DMODEL + d] = c ? (sum / (float)c + tok_b[d]) : 0.0f;
}

// ---------------- launch ----------------
extern "C" void kernel_launch(void* const* d_in, const int* in_sizes, int n_in,
                              void* d_out, int out_size) {
    int shift = (in_sizes[4] == 1) ? 1 : 0;
    const float* c_atom    = (const float*)d_in[0];
    const float* p_lm      = (const float*)d_in[1];
    const int*   p_lm_idx  = (const int*)  d_in[2];
    const int*   token_idx = (const int*)  d_in[3];
    const float* ln_attn_g = (const float*)d_in[4+shift];
    const float* ln_attn_b = (const float*)d_in[5+shift];
    const float* w_q       = (const float*)d_in[6+shift];
    const float* w_k       = (const float*)d_in[7+shift];
    const float* w_v       = (const float*)d_in[8+shift];
    const float* w_g       = (const float*)d_in[9+shift];
    const float* w_o       = (const float*)d_in[10+shift];
    const float* pb_w      = (const float*)d_in[11+shift];
    const float* pb_b      = (const float*)d_in[12+shift];
    const float* ln_ff_g   = (const float*)d_in[13+shift];
    const float* ln_ff_b   = (const float*)d_in[14+shift];
    const float* sw_w1     = (const float*)d_in[15+shift];
    const float* sw_w2     = (const float*)d_in[16+shift];
    const float* sw_w3     = (const float*)d_in[17+shift];
    const float* tok_w     = (const float*)d_in[18+shift];
    const float* tok_b     = (const float*)d_in[19+shift];
    float* out = (float*)d_out;

    float *p_qn, *p_qkvg, *p_attout, *p_q1, *p_h, *p_u, *p_feat;
    cudaGetSymbolAddress((void**)&p_qn,     g_qn);
    cudaGetSymbolAddress((void**)&p_qkvg,   g_qkvg);
    cudaGetSymbolAddress((void**)&p_attout, g_attout);
    cudaGetSymbolAddress((void**)&p_q1,     g_q1);
    cudaGetSymbolAddress((void**)&p_h,      g_h);
    cudaGetSymbolAddress((void**)&p_u,      g_u);
    cudaGetSymbolAddress((void**)&p_feat,   g_feat);

    // group ranges + compact bias scatter
    k_groups<<<ROWS/256, 256>>>(token_idx);
    k_zeroc<<<(ROWS*MAXG + 255)/256, 256>>>();
    k_scatmax<<<(BATCH*NPAIR)/256, 256>>>(p_lm_idx, token_idx);
    k_scatwrite<<<(BATCH*NPAIR)/256, 256>>>(p_lm_idx, token_idx, p_lm, pb_w, pb_b);

    // 1. q_n = LN(c_atom)
    k_ln<<<ROWS/4, 128>>>(c_atom, ln_attn_g, ln_attn_b, p_qn);

    // 2. fused QKVG projection (tensor cores, split-bf16)
    k_mma<128,128,1><<<dim3(8, ROWS/128), 256>>>(p_qn, 128, w_q, w_k, w_v, w_g, 128,
                                                 p_qkvg, 512, nullptr);

    // 3. block-diagonal attention
    k_attn<<<ROWS, 128>>>();

    // 4. w_o projection + gated residual (fused epilogue)
    k_mma<64,128,2><<<dim3(2, ROWS/64), 256>>>(p_attout, 128, w_o, w_o, w_o, w_o, 128,
                                               nullptr, 0, c_atom);

    // 5. FFN: LN -> dual GEMM + SwiGLU -> w3 GEMM + residual add
    k_ln<<<ROWS/4, 128>>>(p_q1, ln_ff_g, ln_ff_b, p_h);
    k_mma_ffn<<<dim3(DFF/64, ROWS/128), 256>>>(p_h, sw_w1, sw_w2);
    k_mma<64,512,4><<<dim3(2, ROWS/64), 256>>>(p_u, 512, sw_w3, sw_w3, sw_w3, sw_w3, 128,
                                               nullptr, 0, nullptr);

    // 6. token projection
    k_mma<128,128,0><<<dim3(DMODEL/64, ROWS/128), 256>>>(p_q1, 128, tok_w, tok_w, tok_w, tok_w,
                                                         512, p_feat, 512, nullptr);

    // 7. segment mean -> output
    k_tokranges<<<(BATCH*NTOK)/256, 256>>>(token_idx);
    k_segmean<<<BATCH*NTOK, DMODEL>>>(tok_b, out);
}

// round 8
// speedup vs baseline: 1.7341x; 1.2450x over previous
#include <cuda_runtime.h>
#include <cuda_bf16.h>
#include <math.h>
#include <stdint.h>

// ---------------- problem constants (fixed shapes) ----------------
#define BATCH   2
#define NATOM   2048
#define DATOM   128
#define NHEAD   4
#define DHEAD   32
#define DFF     512
#define DMODEL  512
#define NPAIR   16384
#define NTOK    512
#define ROWS    (BATCH*NATOM)      // 4096
#define MAXG    96                 // max atoms per token group (avg ~4; 96 astronomically safe)

// ---------------- static device scratch ----------------
__device__ float g_qn    [ROWS*DATOM];
__device__ float g_qkvg  [ROWS*4*DATOM];      // [Q|K|V|G] per row, stride 512
__device__ float g_attout[ROWS*DATOM];
__device__ float g_q1    [ROWS*DATOM];
__device__ float g_h     [ROWS*DATOM];
__device__ float g_u     [ROWS*DFF];
__device__ float g_feat  [ROWS*DMODEL];
__device__ __align__(16) float g_biasc[(size_t)ROWS*MAXG*NHEAD];  // compact in-group bias
__device__ __align__(16) int   g_winc [(size_t)ROWS*MAXG];        // last-write-wins winner
__device__ int   g_gs[ROWS], g_ge[ROWS];
__device__ int   g_ts[BATCH*NTOK], g_tc[BATCH*NTOK];

// ---------------- helpers ----------------
__device__ __forceinline__ int d_lower_bound(const int* a, int n, int v) {
    int lo = 0, hi = n;
    while (lo < hi) { int m = (lo + hi) >> 1; if (a[m] < v) lo = m + 1; else hi = m; }
    return lo;
}
__device__ __forceinline__ int d_upper_bound(const int* a, int n, int v) {
    int lo = 0, hi = n;
    while (lo < hi) { int m = (lo + hi) >> 1; if (a[m] <= v) lo = m + 1; else hi = m; }
    return lo;
}
__device__ __forceinline__ float d_sigmoid(float x) { return 1.0f / (1.0f + __expf(-x)); }

__device__ __forceinline__ void mma_bf16(float d[4], const uint32_t a[4], const uint32_t b[2]) {
    asm volatile(
        "mma.sync.aligned.m16n8k16.row.col.f32.bf16.bf16.f32 "
        "{%0,%1,%2,%3}, {%4,%5,%6,%7}, {%8,%9}, {%0,%1,%2,%3};\n"
        : "+f"(d[0]), "+f"(d[1]), "+f"(d[2]), "+f"(d[3])
        : "r"(a[0]), "r"(a[1]), "r"(a[2]), "r"(a[3]), "r"(b[0]), "r"(b[1]));
}
__device__ __forceinline__ void cvt_hl(float x, unsigned short& h, unsigned short& l) {
    __nv_bfloat16 hb = __float2bfloat16(x);
    float r = x - __bfloat162float(hb);
    h = __bfloat16_as_ushort(hb);
    l = __bfloat16_as_ushort(__float2bfloat16(r));
}

// ---------------- LayerNorm: one warp per row of 128 ----------------
__global__ void k_ln(const float* __restrict__ x, const float* __restrict__ g,
                     const float* __restrict__ b, float* __restrict__ y) {
    int warp = (blockIdx.x * blockDim.x + threadIdx.x) >> 5;
    int lane = threadIdx.x & 31;
    if (warp >= ROWS) return;
    const float* xr = x + (size_t)warp * DATOM;
    float v0 = xr[lane], v1 = xr[lane+32], v2 = xr[lane+64], v3 = xr[lane+96];
    float s  = v0+v1+v2+v3;
    float sq = v0*v0+v1*v1+v2*v2+v3*v3;
    #pragma unroll
    for (int o = 16; o; o >>= 1) {
        s  += __shfl_xor_sync(0xffffffffu, s,  o);
        sq += __shfl_xor_sync(0xffffffffu, sq, o);
    }
    float mean = s * (1.0f/DATOM);
    float var  = sq * (1.0f/DATOM) - mean*mean;
    float inv  = rsqrtf(var + 1e-5f);
    float* yr = y + (size_t)warp * DATOM;
    yr[lane]    = (v0-mean)*inv*g[lane]    + b[lane];
    yr[lane+32] = (v1-mean)*inv*g[lane+32] + b[lane+32];
    yr[lane+64] = (v2-mean)*inv*g[lane+64] + b[lane+64];
    yr[lane+96] = (v3-mean)*inv*g[lane+96] + b[lane+96];
}

// ============================================================================
// Split-bf16 tensor-core GEMM with FULL-K smem residency (dynamic smem).
// Block tile BM x 64. K processed in KTILES chunks of 128. One sync per chunk.
// EPI: 0 = store C; 1 = qkvg weight-select; 2 = wo gated-residual; 4 = w3 res-add
// ============================================================================
#define AST 136   // smem K-stride (bf16 elems): 136*2B/4 = 68 words, 68%32=4 -> conflict-free frags

template<int BM, int KTILES, int EPI>
__global__ __launch_bounds__(256) void k_mma(
    const float* __restrict__ A, int lda,
    const float* __restrict__ B0, const float* __restrict__ B1t,
    const float* __restrict__ B2t, const float* __restrict__ B3t,
    int ldb, float* __restrict__ C, int ldc, const float* __restrict__ aux) {
    constexpr int WR  = (BM == 128) ? 4 : 2;
    constexpr int WTM = BM / WR;            // 32
    constexpr int WTN = 64 / (8 / WR);      // 32 (BM=128) or 16 (BM=64)
    constexpr int MT  = WTM / 16;           // 2
    constexpr int NT  = WTN / 8;            // 4 or 2

    extern __shared__ __align__(16) char smraw[];
    __nv_bfloat16* Ah = (__nv_bfloat16*)smraw;
    __nv_bfloat16* Al = Ah + BM*AST;
    __nv_bfloat16* Bh = Al + BM*AST;
    __nv_bfloat16* Bl = Bh + 64*AST;

    int tid = threadIdx.x, warp = tid >> 5, lane = tid & 31;
    int wm = warp % WR, wn = warp / WR;
    int gq = lane >> 2, t4 = lane & 3;
    int bm = blockIdx.y * BM;

    const float* Bsel; int bn;
    if (EPI == 1) {
        int wi = blockIdx.x >> 1;
        Bsel = (wi == 0) ? B0 : (wi == 1) ? B1t : (wi == 2) ? B2t : B3t;
        bn = (blockIdx.x & 1) * 64;
    } else { Bsel = B0; bn = blockIdx.x * 64; }
    int cn = blockIdx.x * 64;

    float acc[MT][NT][4] = {};

    for (int kt = 0; kt < KTILES; kt++) {
        // ---- load + split A tile: BM x 128 fp32 ----
        #pragma unroll
        for (int it = 0; it < BM/8; it++) {
            int idx = tid + it*256;
            int r = idx >> 5, c4 = (idx & 31) << 2;
            float4 v = *(const float4*)(A + (size_t)(bm + r) * lda + kt*128 + c4);
            unsigned short h0,l0,h1,l1,h2,l2,h3,l3;
            cvt_hl(v.x,h0,l0); cvt_hl(v.y,h1,l1); cvt_hl(v.z,h2,l2); cvt_hl(v.w,h3,l3);
            *(uint32_t*)&Ah[r*AST + c4    ] = (uint32_t)h0 | ((uint32_t)h1 << 16);
            *(uint32_t*)&Ah[r*AST + c4 + 2] = (uint32_t)h2 | ((uint32_t)h3 << 16);
            *(uint32_t*)&Al[r*AST + c4    ] = (uint32_t)l0 | ((uint32_t)l1 << 16);
            *(uint32_t*)&Al[r*AST + c4 + 2] = (uint32_t)l2 | ((uint32_t)l3 << 16);
        }
        // ---- load + split B tile: 128(K) x 64(N) fp32, store K-major per col ----
        #pragma unroll
        for (int it = 0; it < 8; it++) {
            int idx = tid + it*256;
            int k = idx >> 4, n4 = (idx & 15) << 2;
            float4 v = *(const float4*)(Bsel + (size_t)(kt*128 + k) * ldb + bn + n4);
            float e[4] = {v.x, v.y, v.z, v.w};
            #pragma unroll
            for (int j = 0; j < 4; j++) {
                __nv_bfloat16 hb = __float2bfloat16(e[j]);
                Bh[(n4+j)*AST + k] = hb;
                Bl[(n4+j)*AST + k] = __float2bfloat16(e[j] - __bfloat162float(hb));
            }
        }
        __syncthreads();

        #pragma unroll
        for (int kk = 0; kk < 8; kk++) {
            int kb = kk * 16;
            uint32_t afh[MT][4], afl[MT][4], bfh[NT][2], bfl[NT][2];
            #pragma unroll
            for (int mt = 0; mt < MT; mt++) {
                int r0 = wm * WTM + mt * 16 + gq;
                afh[mt][0] = *(const uint32_t*)&Ah[ r0      *AST + kb + 2*t4    ];
                afh[mt][1] = *(const uint32_t*)&Ah[(r0 + 8) *AST + kb + 2*t4    ];
                afh[mt][2] = *(const uint32_t*)&Ah[ r0      *AST + kb + 2*t4 + 8];
                afh[mt][3] = *(const uint32_t*)&Ah[(r0 + 8) *AST + kb + 2*t4 + 8];
                afl[mt][0] = *(const uint32_t*)&Al[ r0      *AST + kb + 2*t4    ];
                afl[mt][1] = *(const uint32_t*)&Al[(r0 + 8) *AST + kb + 2*t4    ];
                afl[mt][2] = *(const uint32_t*)&Al[ r0      *AST + kb + 2*t4 + 8];
                afl[mt][3] = *(const uint32_t*)&Al[(r0 + 8) *AST + kb + 2*t4 + 8];
            }
            #pragma unroll
            for (int nt = 0; nt < NT; nt++) {
                int c0 = wn * WTN + nt * 8 + gq;
                bfh[nt][0] = *(const uint32_t*)&Bh[c0*AST + kb + 2*t4    ];
                bfh[nt][1] = *(const uint32_t*)&Bh[c0*AST + kb + 2*t4 + 8];
                bfl[nt][0] = *(const uint32_t*)&Bl[c0*AST + kb + 2*t4    ];
                bfl[nt][1] = *(const uint32_t*)&Bl[c0*AST + kb + 2*t4 + 8];
            }
            #pragma unroll
            for (int mt = 0; mt < MT; mt++)
                #pragma unroll
                for (int nt = 0; nt < NT; nt++) {
                    mma_bf16(acc[mt][nt], afh[mt], bfh[nt]);
                    mma_bf16(acc[mt][nt], afh[mt], bfl[nt]);
                    mma_bf16(acc[mt][nt], afl[mt], bfh[nt]);
                }
        }
        if (KTILES > 1) __syncthreads();
    }

    // ---- epilogue ----
    #pragma unroll
    for (int mt = 0; mt < MT; mt++)
        #pragma unroll
        for (int nt = 0; nt < NT; nt++)
            #pragma unroll
            for (int ci = 0; ci < 4; ci++) {
                int r = bm + wm * WTM + mt * 16 + gq + ((ci >> 1) ? 8 : 0);
                int c = cn + wn * WTN + nt * 8 + 2 * t4 + (ci & 1);
                float v = acc[mt][nt][ci];
                if constexpr (EPI == 0 || EPI == 1) {
                    C[(size_t)r * ldc + c] = v;
                } else if constexpr (EPI == 2) {
                    float gt = g_qkvg[(size_t)r * 512 + 3*DATOM + c];
                    g_q1[(size_t)r * DATOM + c] =
                        aux[(size_t)r * DATOM + c] + d_sigmoid(gt) * v;
                } else if constexpr (EPI == 4) {
                    g_q1[(size_t)r * DATOM + c] += v;
                }
            }
}

// ---------- dual-B FFN MMA: g_u = silu(h@w1) * (h@w2), BM=128, K=128, full-K smem ----------
__global__ __launch_bounds__(256) void k_mma_ffn(
    const float* __restrict__ A,
    const float* __restrict__ W1, const float* __restrict__ W2) {
    extern __shared__ __align__(16) char smraw[];
    __nv_bfloat16* Ah  = (__nv_bfloat16*)smraw;
    __nv_bfloat16* Al  = Ah  + 128*AST;
    __nv_bfloat16* B1h = Al  + 128*AST;
    __nv_bfloat16* B1l = B1h + 64*AST;
    __nv_bfloat16* B2h = B1l + 64*AST;
    __nv_bfloat16* B2l = B2h + 64*AST;

    int tid = threadIdx.x, warp = tid >> 5, lane = tid & 31;
    int wm = warp & 3, wn = warp >> 2;           // 4x2 warps, warptile 32x32
    int gq = lane >> 2, t4 = lane & 3;
    int bm = blockIdx.y * 128;
    int bn = blockIdx.x * 64;

    float au[2][4][4] = {}, avv[2][4][4] = {};

    // ---- load + split A (128x128) ----
    #pragma unroll
    for (int it = 0; it < 16; it++) {
        int idx = tid + it*256;
        int r = idx >> 5, c4 = (idx & 31) << 2;
        float4 v = *(const float4*)(A + (size_t)(bm + r) * 128 + c4);
        unsigned short h0,l0,h1,l1,h2,l2,h3,l3;
        cvt_hl(v.x,h0,l0); cvt_hl(v.y,h1,l1); cvt_hl(v.z,h2,l2); cvt_hl(v.w,h3,l3);
        *(uint32_t*)&Ah[r*AST + c4    ] = (uint32_t)h0 | ((uint32_t)h1 << 16);
        *(uint32_t*)&Ah[r*AST + c4 + 2] = (uint32_t)h2 | ((uint32_t)h3 << 16);
        *(uint32_t*)&Al[r*AST + c4    ] = (uint32_t)l0 | ((uint32_t)l1 << 16);
        *(uint32_t*)&Al[r*AST + c4 + 2] = (uint32_t)l2 | ((uint32_t)l3 << 16);
    }
    // ---- load + split B1, B2 (128K x 64N) ----
    #pragma unroll
    for (int it = 0; it < 8; it++) {
        int idx = tid + it*256;
        int k = idx >> 4, n4 = (idx & 15) << 2;
        float4 v1 = *(const float4*)(W1 + (size_t)k * DFF + bn + n4);
        float4 v2 = *(const float4*)(W2 + (size_t)k * DFF + bn + n4);
        float e1[4] = {v1.x,v1.y,v1.z,v1.w}, e2[4] = {v2.x,v2.y,v2.z,v2.w};
        #pragma unroll
        for (int j = 0; j < 4; j++) {
            __nv_bfloat16 hb = __float2bfloat16(e1[j]);
            B1h[(n4+j)*AST + k] = hb;
            B1l[(n4+j)*AST + k] = __float2bfloat16(e1[j] - __bfloat162float(hb));
            __nv_bfloat16 hb2 = __float2bfloat16(e2[j]);
            B2h[(n4+j)*AST + k] = hb2;
            B2l[(n4+j)*AST + k] = __float2bfloat16(e2[j] - __bfloat162float(hb2));
        }
    }
    __syncthreads();

    #pragma unroll
    for (int kk = 0; kk < 8; kk++) {
        int kb = kk * 16;
        uint32_t afh[2][4], afl[2][4];
        #pragma unroll
        for (int mt = 0; mt < 2; mt++) {
            int r0 = wm * 32 + mt * 16 + gq;
            afh[mt][0] = *(const uint32_t*)&Ah[ r0     *AST + kb + 2*t4    ];
            afh[mt][1] = *(const uint32_t*)&Ah[(r0 + 8)*AST + kb + 2*t4    ];
            afh[mt][2] = *(const uint32_t*)&Ah[ r0     *AST + kb + 2*t4 + 8];
            afh[mt][3] = *(const uint32_t*)&Ah[(r0 + 8)*AST + kb + 2*t4 + 8];
            afl[mt][0] = *(const uint32_t*)&Al[ r0     *AST + kb + 2*t4    ];
            afl[mt][1] = *(const uint32_t*)&Al[(r0 + 8)*AST + kb + 2*t4    ];
            afl[mt][2] = *(const uint32_t*)&Al[ r0     *AST + kb + 2*t4 + 8];
            afl[mt][3] = *(const uint32_t*)&Al[(r0 + 8)*AST + kb + 2*t4 + 8];
        }
        #pragma unroll
        for (int nt = 0; nt < 4; nt++) {
            int c0 = wn * 32 + nt * 8 + gq;
            uint32_t b1f[2] = {*(const uint32_t*)&B1h[c0*AST + kb + 2*t4], *(const uint32_t*)&B1h[c0*AST + kb + 2*t4 + 8]};
            uint32_t b1g[2] = {*(const uint32_t*)&B1l[c0*AST + kb + 2*t4], *(const uint32_t*)&B1l[c0*AST + kb + 2*t4 + 8]};
            uint32_t b2f[2] = {*(const uint32_t*)&B2h[c0*AST + kb + 2*t4], *(const uint32_t*)&B2h[c0*AST + kb + 2*t4 + 8]};
            uint32_t b2g[2] = {*(const uint32_t*)&B2l[c0*AST + kb + 2*t4], *(const uint32_t*)&B2l[c0*AST + kb + 2*t4 + 8]};
            #pragma unroll
            for (int mt = 0; mt < 2; mt++) {
                mma_bf16(au [mt][nt], afh[mt], b1f);
                mma_bf16(au [mt][nt], afh[mt], b1g);
                mma_bf16(au [mt][nt], afl[mt], b1f);
                mma_bf16(avv[mt][nt], afh[mt], b2f);
                mma_bf16(avv[mt][nt], afh[mt], b2g);
                mma_bf16(avv[mt][nt], afl[mt], b2f);
            }
        }
    }
    #pragma unroll
    for (int mt = 0; mt < 2; mt++)
        #pragma unroll
        for (int nt = 0; nt < 4; nt++)
            #pragma unroll
            for (int ci = 0; ci < 4; ci++) {
                int r = bm + wm * 32 + mt * 16 + gq + ((ci >> 1) ? 8 : 0);
                int c = bn + wn * 32 + nt * 8 + 2 * t4 + (ci & 1);
                float uu = au[mt][nt][ci];
                g_u[(size_t)r * DFF + c] = (uu * d_sigmoid(uu)) * avv[mt][nt][ci];
            }
}

// ---------------- fused prep: group ranges + token ranges + winner zero ----------------
__global__ void k_prep(const int* __restrict__ tok) {
    int idx = blockIdx.x * blockDim.x + threadIdx.x;
    if (idx < ROWS*MAXG/4)
        ((int4*)g_winc)[idx] = make_int4(-1, -1, -1, -1);
    if (idx < ROWS) {
        int b = idx / NATOM, ii = idx % NATOM;
        const int* t = tok + b * NATOM;
        int v = t[ii];
        g_gs[idx] = d_lower_bound(t, NATOM, v);
        g_ge[idx] = d_upper_bound(t, NATOM, v);
    }
    if (idx < BATCH*NTOK) {
        int b = idx / NTOK, tt = idx % NTOK;
        const int* ta = tok + b * NATOM;
        int lo = d_lower_bound(ta, NATOM, tt);
        int hi = d_upper_bound(ta, NATOM, tt);
        g_ts[idx] = lo; g_tc[idx] = hi - lo;
    }
}

// ---------------- pair scatter pass 1: last-write-wins winner ----------------
__global__ void k_scatmax(const int* __restrict__ plmidx, const int* __restrict__ tok) {
    int gid = blockIdx.x * blockDim.x + threadIdx.x;
    if (gid >= BATCH * NPAIR) return;
    int b = gid / NPAIR, p = gid % NPAIR;
    int src = plmidx[(size_t)gid*2], dst = plmidx[(size_t)gid*2 + 1];
    if (tok[b*NATOM + src] != tok[b*NATOM + dst]) return;
    int i = b*NATOM + src;
    int slot = dst - g_gs[i];
    if (slot >= 0 && slot < MAXG)
        atomicMax(&g_winc[(size_t)i * MAXG + slot], p);
}

// ---------------- pass 2: slot-ordered bias fill (coalesced; zeros losers) ----------------
__global__ void k_biasfill(const float* __restrict__ p_lm,
                           const float* __restrict__ pb_w, const float* __restrict__ pb_b) {
    int slot = blockIdx.x * blockDim.x + threadIdx.x;
    if (slot >= ROWS * MAXG) return;
    int w = g_winc[slot];
    float4 v = make_float4(0.f, 0.f, 0.f, 0.f);
    if (w >= 0) {
        int i = slot / MAXG;
        int b = i / NATOM;
        const float* pl = p_lm + ((size_t)b * NPAIR + w) * 16;
        float h0 = pb_b[0], h1 = pb_b[1], h2 = pb_b[2], h3 = pb_b[3];
        #pragma unroll
        for (int k = 0; k < 16; k++) {
            float plk = pl[k];
            h0 += plk * pb_w[k*NHEAD + 0];
            h1 += plk * pb_w[k*NHEAD + 1];
            h2 += plk * pb_w[k*NHEAD + 2];
            h3 += plk * pb_w[k*NHEAD + 3];
        }
        v = make_float4(h0, h1, h2, h3);
    }
    ((float4*)g_biasc)[slot] = v;
}

// ---------------- block-diagonal attention: 1 block/atom, 1 warp/head ----------------
__global__ void k_attn() {
    int i = blockIdx.x;
    int b = i / NATOM;
    int h = threadIdx.x >> 5, lane = threadIdx.x & 31;
    int s = g_gs[i], e = g_ge[i];
    const float* qrow = g_qkvg + (size_t)i * 512;
    float qd = qrow[h*DHEAD + lane];
    const float* biasrow = g_biasc + (size_t)i * MAXG * NHEAD + h;
    float m = -1e30f, l = 0.0f, acc = 0.0f;
    for (int j = s; j < e; j++) {
        const float* row = g_qkvg + (size_t)(b*NATOM + j) * 512;
        float sc = qd * row[DATOM + h*DHEAD + lane];
        #pragma unroll
        for (int o = 16; o; o >>= 1) sc += __shfl_xor_sync(0xffffffffu, sc, o);
        int slot = j - s;
        float bias = (slot < MAXG) ? biasrow[(size_t)slot * NHEAD] : 0.0f;
        sc = sc * 0.17677669529663687f + bias;
        float mn = fmaxf(m, sc);
        float corr = __expf(m - mn);
        float w = __expf(sc - mn);
        l = l * corr + w;
        acc = acc * corr + w * row[2*DATOM + h*DHEAD + lane];
        m = mn;
    }
    g_attout[(size_t)i * DATOM + h*DHEAD + lane] = acc / l;
}

// ---------------- segment mean ----------------
__global__ void k_segmean(const float* __restrict__ tok_b, float* __restrict__ out) {
    int seg = blockIdx.x;
    int b = seg / NTOK;
    int d = threadIdx.x;
    int s = g_ts[seg], c = g_tc[seg];
    float sum = 0.0f;
    for (int k = 0; k < c; k++)
        sum += g_feat[(size_t)(b*NATOM + s + k) * DMODEL + d];
    out[(size_t)seg * DMODEL + d] = c ? (sum / (float)c + tok_b[d]) : 0.0f;
}

// ---------------- launch ----------------
extern "C" void kernel_launch(void* const* d_in, const int* in_sizes, int n_in,
                              void* d_out, int out_size) {
    int shift = (in_sizes[4] == 1) ? 1 : 0;
    const float* c_atom    = (const float*)d_in[0];
    const float* p_lm      = (const float*)d_in[1];
    const int*   p_lm_idx  = (const int*)  d_in[2];
    const int*   token_idx = (const int*)  d_in[3];
    const float* ln_attn_g = (const float*)d_in[4+shift];
    const float* ln_attn_b = (const float*)d_in[5+shift];
    const float* w_q       = (const float*)d_in[6+shift];
    const float* w_k       = (const float*)d_in[7+shift];
    const float* w_v       = (const float*)d_in[8+shift];
    const float* w_g       = (const float*)d_in[9+shift];
    const float* w_o       = (const float*)d_in[10+shift];
    const float* pb_w      = (const float*)d_in[11+shift];
    const float* pb_b      = (const float*)d_in[12+shift];
    const float* ln_ff_g   = (const float*)d_in[13+shift];
    const float* ln_ff_b   = (const float*)d_in[14+shift];
    const float* sw_w1     = (const float*)d_in[15+shift];
    const float* sw_w2     = (const float*)d_in[16+shift];
    const float* sw_w3     = (const float*)d_in[17+shift];
    const float* tok_w     = (const float*)d_in[18+shift];
    const float* tok_b     = (const float*)d_in[19+shift];
    float* out = (float*)d_out;

    float *p_qn, *p_qkvg, *p_attout, *p_q1, *p_h, *p_u, *p_feat;
    cudaGetSymbolAddress((void**)&p_qn,     g_qn);
    cudaGetSymbolAddress((void**)&p_qkvg,   g_qkvg);
    cudaGetSymbolAddress((void**)&p_attout, g_attout);
    cudaGetSymbolAddress((void**)&p_q1,     g_q1);
    cudaGetSymbolAddress((void**)&p_h,      g_h);
    cudaGetSymbolAddress((void**)&p_u,      g_u);
    cudaGetSymbolAddress((void**)&p_feat,   g_feat);

    // dynamic smem opt-in (idempotent)
    const int SM128 = 2 * AST * (128 + 64) * 2;   // 104448 B
    const int SM64  = 2 * AST * ( 64 + 64) * 2;   //  69632 B
    const int SMFFN = 2 * AST * (128 + 128) * 2;  // 139264 B
    cudaFuncSetAttribute(k_mma<128,1,1>, cudaFuncAttributeMaxDynamicSharedMemorySize, SM128);
    cudaFuncSetAttribute(k_mma<128,1,0>, cudaFuncAttributeMaxDynamicSharedMemorySize, SM128);
    cudaFuncSetAttribute(k_mma<64,1,2>,  cudaFuncAttributeMaxDynamicSharedMemorySize, SM64);
    cudaFuncSetAttribute(k_mma<64,4,4>,  cudaFuncAttributeMaxDynamicSharedMemorySize, SM64);
    cudaFuncSetAttribute(k_mma_ffn,      cudaFuncAttributeMaxDynamicSharedMemorySize, SMFFN);

    // side stream for the bias chain (created once; same work every call)
    static cudaStream_t s_side = nullptr;
    static cudaEvent_t  e_fork = nullptr, e_join = nullptr;
    if (!s_side) {
        cudaStreamCreateWithFlags(&s_side, cudaStreamNonBlocking);
        cudaEventCreateWithFlags(&e_fork, cudaEventDisableTiming);
        cudaEventCreateWithFlags(&e_join, cudaEventDisableTiming);
    }

    // ---- fork: bias chain on side stream, overlapped with LN+QKVG ----
    cudaEventRecord(e_fork, 0);
    cudaStreamWaitEvent(s_side, e_fork, 0);
    k_prep    <<<ROWS*MAXG/4/256, 256, 0, s_side>>>(token_idx);
    k_scatmax <<<(BATCH*NPAIR)/256, 256, 0, s_side>>>(p_lm_idx, token_idx);
    k_biasfill<<<ROWS*MAXG/256, 256, 0, s_side>>>(p_lm, pb_w, pb_b);
    cudaEventRecord(e_join, s_side);

    // ---- main chain ----
    k_ln<<<ROWS/4, 128>>>(c_atom, ln_attn_g, ln_attn_b, p_qn);
    k_mma<128,1,1><<<dim3(8, ROWS/128), 256, SM128>>>(p_qn, 128, w_q, w_k, w_v, w_g, 128,
                                                      p_qkvg, 512, nullptr);

    // join bias chain, then attention
    cudaStreamWaitEvent(0, e_join, 0);
    k_attn<<<ROWS, 128>>>();

    k_mma<64,1,2><<<dim3(2, ROWS/64), 256, SM64>>>(p_attout, 128, w_o, w_o, w_o, w_o, 128,
                                                   nullptr, 0, c_atom);
    k_ln<<<ROWS/4, 128>>>(p_q1, ln_ff_g, ln_ff_b, p_h);
    k_mma_ffn<<<dim3(DFF/64, ROWS/128), 256, SMFFN>>>(p_h, sw_w1, sw_w2);
    k_mma<64,4,4><<<dim3(2, ROWS/64), 256, SM64>>>(p_u, 512, sw_w3, sw_w3, sw_w3, sw_w3, 128,
                                                   nullptr, 0, nullptr);
    k_mma<128,1,0><<<dim3(DMODEL/64, ROWS/128), 256, SM128>>>(p_q1, 128, tok_w, tok_w, tok_w, tok_w,
                                                              512, p_feat, 512, nullptr);
    k_segmean<<<BATCH*NTOK, DMODEL>>>(tok_b, out);
}